// round 10
// baseline (speedup 1.0000x reference)
#include <cuda_runtime.h>
#include <cuda_bf16.h>

// Problem dims
#define SL 512   // sequence length L
#define NB 64    // batch
#define NE 256   // embed dim E
#define NH 256   // hidden H
#define NG 1024  // 4*H
#define NT 32    // tags T

// ---------------------------------------------------------------------------
// Packed f32x2 helpers (sm_103a; ptxas never auto-emits FFMA2)
// ---------------------------------------------------------------------------
#define FMA2(acc, a, b) \
    asm("fma.rn.f32x2 %0, %1, %2, %0;" : "+l"(acc) : "l"(a), "l"(b))
#define ADD2(acc, v) \
    asm("add.rn.f32x2 %0, %0, %1;" : "+l"(acc) : "l"(v))
#define DUP2(d, s) do { unsigned _u = __float_as_uint(s); \
    asm("mov.b64 %0, {%1, %1};" : "=l"(d) : "r"(_u)); } while (0)
#define UNPK2(lo, hi, v) do { unsigned _a, _b; \
    asm("mov.b64 {%0, %1}, %2;" : "=r"(_a), "=r"(_b) : "l"(v)); \
    lo = __uint_as_float(_a); hi = __uint_as_float(_b); } while (0)

// ---------------------------------------------------------------------------
// Device-global scratch
// ---------------------------------------------------------------------------
__device__ float    g_xproj[2][(size_t)SL * NB * NG];
__device__ float    g_hout [2][(size_t)SL * NB * NH];
__device__ float    g_em   [(size_t)SL * NB * NT];
__device__ float    g_hbuf [2][2][NB * NH];
__device__ float    g_WoutT[512 * NT];
__device__ float    g_llh  [NB];
__device__ unsigned g_gcnt[16 * 32];   // group barrier counters (cacheline spaced)
__device__ unsigned g_ggen[16 * 32];   // group barrier generations

// ---------------------------------------------------------------------------
// 8-block group barrier (dir x batch-octet). Generation-relative, so state
// carries across graph replays safely.
// ---------------------------------------------------------------------------
__device__ __forceinline__ void groupbar(int gid) {
    __threadfence();
    __syncthreads();
    if (threadIdx.x == 0) {
        volatile unsigned* vgen = &g_ggen[gid * 32];
        unsigned gen = *vgen;
        unsigned t = atomicAdd(&g_gcnt[gid * 32], 1u);
        if (t == 7u) {
            g_gcnt[gid * 32] = 0u;
            __threadfence();
            *vgen = gen + 1u;
        } else {
            while (*vgen == gen) { }
        }
        __threadfence();
    }
    __syncthreads();
}

// ---------------------------------------------------------------------------
// Kernel 1: x_proj = gather(embed, seqs) @ W_ih^T + (b_ih + b_hh)
// Tile 64x64x16, 256 thr, 4x4 microtile, FFMA2 packed over n-pairs.
// ---------------------------------------------------------------------------
__global__ __launch_bounds__(256) void xproj_kernel(
    const float* __restrict__ embed, const int* __restrict__ seqs,
    const float* __restrict__ Wf, const float* __restrict__ Wb,
    const float* __restrict__ bihf, const float* __restrict__ bhhf,
    const float* __restrict__ bihb, const float* __restrict__ bhhb)
{
    __shared__ float As[16][64];
    __shared__ float Bs[16][64];

    const int dir = blockIdx.z;
    const float* W  = dir ? Wb   : Wf;
    const float* b1 = dir ? bihb : bihf;
    const float* b2 = dir ? bhhb : bhhf;
    float* out = g_xproj[dir];

    const int tid = threadIdx.x;
    const int bn = blockIdx.x;
    const int bm = blockIdx.y;
    const int tx = tid & 15;
    const int ty = tid >> 4;
    const int lr = tid & 63;
    const int kq = (tid >> 6) * 4;

    const long arow = (long)seqs[bm * 64 + lr] * 256;
    const float* Brow = W + (long)(bn * 64 + lr) * 256;

    unsigned long long acc2[4][2];
#pragma unroll
    for (int i = 0; i < 4; i++) { acc2[i][0] = 0ull; acc2[i][1] = 0ull; }

    for (int k0 = 0; k0 < 256; k0 += 16) {
        float4 a = *(const float4*)(embed + arow + k0 + kq);
        float4 b = *(const float4*)(Brow + k0 + kq);
        __syncthreads();
        As[kq + 0][lr] = a.x; As[kq + 1][lr] = a.y;
        As[kq + 2][lr] = a.z; As[kq + 3][lr] = a.w;
        Bs[kq + 0][lr] = b.x; Bs[kq + 1][lr] = b.y;
        Bs[kq + 2][lr] = b.z; Bs[kq + 3][lr] = b.w;
        __syncthreads();
#pragma unroll
        for (int k = 0; k < 16; k++) {
            float4 av = *(const float4*)&As[k][ty * 4];
            ulonglong2 bv = *(const ulonglong2*)&Bs[k][tx * 4];
            unsigned long long a0, a1, a2, a3;
            DUP2(a0, av.x); DUP2(a1, av.y); DUP2(a2, av.z); DUP2(a3, av.w);
            FMA2(acc2[0][0], a0, bv.x); FMA2(acc2[0][1], a0, bv.y);
            FMA2(acc2[1][0], a1, bv.x); FMA2(acc2[1][1], a1, bv.y);
            FMA2(acc2[2][0], a2, bv.x); FMA2(acc2[2][1], a2, bv.y);
            FMA2(acc2[3][0], a3, bv.x); FMA2(acc2[3][1], a3, bv.y);
        }
    }

    const int ng = bn * 64 + tx * 4;
    float4 bias;
    bias.x = b1[ng + 0] + b2[ng + 0];
    bias.y = b1[ng + 1] + b2[ng + 1];
    bias.z = b1[ng + 2] + b2[ng + 2];
    bias.w = b1[ng + 3] + b2[ng + 3];
#pragma unroll
    for (int i = 0; i < 4; i++) {
        long r = (long)bm * 64 + ty * 4 + i;
        float4 o;
        UNPK2(o.x, o.y, acc2[i][0]);
        UNPK2(o.z, o.w, acc2[i][1]);
        o.x += bias.x; o.y += bias.y; o.z += bias.z; o.w += bias.w;
        *(float4*)(out + r * 1024 + ng) = o;
    }
}

// ---------------------------------------------------------------------------
// Kernel 2: persistent BiLSTM. 128 blocks, 256 thr; block = 8 batch x 32
// hidden. FFMA2 packed over k-pairs; packed psum reduce; 8-block group
// barrier per (dir, batch-octet).
// ---------------------------------------------------------------------------
#define LSTM_NBLK 128u
// floats: wsm 32768 + psumU (8192 ull = 16384 floats) + hsm 2048
#define LSTM_SMEM_BYTES ((32768 + 16384 + 2048) * 4)

__global__ __launch_bounds__(256, 1) void lstm_kernel(
    const float* __restrict__ Whhf, const float* __restrict__ Whhb,
    const int* __restrict__ masks)
{
    extern __shared__ float sm[];
    float*              wsm   = sm;                        // [128][64 f4], swizzled
    unsigned long long* psumU = (unsigned long long*)(sm + 32768); // [8][32][32]
    float*              hsm   = sm + 32768 + 16384;        // [8][256]
    float4*      wsm4 = (float4*)wsm;
    ulonglong2*  wsmU = (ulonglong2*)wsm;
    float4*      hsm4 = (float4*)hsm;
    ulonglong2*  hsmU = (ulonglong2*)hsm;

    const int tid  = threadIdx.x;
    const int w    = tid >> 5;
    const int lane = tid & 31;
    const int blk  = blockIdx.x;
    const int dir  = blk >> 6;
    const int sub  = blk & 63;
    const int b0   = (sub >> 3) * 8;
    const int h0   = (sub & 7) * 32;
    const int gid  = dir * 8 + (sub >> 3);   // barrier group
    const int hh   = lane;
    const int bb   = w;

    const float* W  = dir ? Whhb : Whhf;
    const float* xp = g_xproj[dir];
    float* outp = g_hout[dir];

    // Load W_hh slice (rows g*NH + h0 + hr), XOR-swizzled by (hr & 7).
    for (int i = 0; i < 32; i++) {
        int idx = tid + i * 256;
        int row = idx >> 6;
        int cg  = idx & 63;
        int g   = row >> 5, hr = row & 31;
        float4 v = *(const float4*)(W + ((size_t)(g * 256 + h0 + hr)) * 256 + cg * 4);
        wsm4[row * 64 + (cg ^ (hr & 7))] = v;
    }
    g_hbuf[dir][0][(b0 + bb) * 256 + h0 + hh] = 0.f;
    float hreg = 0.f, creg = 0.f;
    groupbar(gid);

    const int xorm = lane & 7;
    int p = 0;
    for (int step = 0; step < 512; step++) {
        const int l = dir ? (511 - step) : step;

        // Prefetch gate pre-activations + mask.
        const float* xr = xp + ((size_t)(l * 64 + b0 + bb)) * 1024 + h0 + hh;
        float x0 = __ldg(xr + 0);
        float x1 = __ldg(xr + 256);
        float x2 = __ldg(xr + 512);
        float x3 = __ldg(xr + 768);
        int   m  = __ldg(masks + l * 64 + b0 + bb);

        // Stage h_prev (8 x 256) from L2.
        const float4* hb = (const float4*)g_hbuf[dir][p];
#pragma unroll
        for (int i = 0; i < 2; i++) {
            int idx = tid + i * 256;
            hsm4[idx] = __ldcg(hb + (b0 + (idx >> 6)) * 64 + (idx & 63));
        }
        __syncthreads();

        // Packed GEMM: lane owns hidden h0+lane; warp owns k-slice of 32.
        unsigned long long acc2[4][8];
#pragma unroll
        for (int g = 0; g < 4; g++)
#pragma unroll
            for (int b = 0; b < 8; b++) acc2[g][b] = 0ull;

#pragma unroll
        for (int j = 0; j < 8; j++) {
            int cg = (w << 3) + j;
            int cs = cg ^ xorm;
            ulonglong2 w0 = wsmU[(0 * 32 + lane) * 64 + cs];
            ulonglong2 w1 = wsmU[(1 * 32 + lane) * 64 + cs];
            ulonglong2 w2 = wsmU[(2 * 32 + lane) * 64 + cs];
            ulonglong2 w3 = wsmU[(3 * 32 + lane) * 64 + cs];
#pragma unroll
            for (int b = 0; b < 8; b++) {
                ulonglong2 hv = hsmU[b * 64 + cg];
                FMA2(acc2[0][b], hv.x, w0.x); FMA2(acc2[0][b], hv.y, w0.y);
                FMA2(acc2[1][b], hv.x, w1.x); FMA2(acc2[1][b], hv.y, w1.y);
                FMA2(acc2[2][b], hv.x, w2.x); FMA2(acc2[2][b], hv.y, w2.y);
                FMA2(acc2[3][b], hv.x, w3.x); FMA2(acc2[3][b], hv.y, w3.y);
            }
        }

        // Packed K-partials.
#pragma unroll
        for (int g = 0; g < 4; g++)
#pragma unroll
            for (int b = 0; b < 8; b++)
                psumU[w * 1024 + (g * 8 + b) * 32 + lane] = acc2[g][b];
        __syncthreads();

        // Packed reduce across warps; thread = (bb, hh).
        unsigned long long s0 = 0ull, s1 = 0ull, s2 = 0ull, s3 = 0ull;
#pragma unroll
        for (int ww = 0; ww < 8; ww++) {
            ADD2(s0, psumU[ww * 1024 + (0 * 8 + bb) * 32 + hh]);
            ADD2(s1, psumU[ww * 1024 + (1 * 8 + bb) * 32 + hh]);
            ADD2(s2, psumU[ww * 1024 + (2 * 8 + bb) * 32 + hh]);
            ADD2(s3, psumU[ww * 1024 + (3 * 8 + bb) * 32 + hh]);
        }
        float lo, hi, f0, f1, f2, f3;
        UNPK2(lo, hi, s0); f0 = lo + hi;
        UNPK2(lo, hi, s1); f1 = lo + hi;
        UNPK2(lo, hi, s2); f2 = lo + hi;
        UNPK2(lo, hi, s3); f3 = lo + hi;

        float gi = 1.f / (1.f + __expf(-(x0 + f0)));
        float gf = 1.f / (1.f + __expf(-(x1 + f1)));
        float gg = tanhf(x2 + f2);
        float go = 1.f / (1.f + __expf(-(x3 + f3)));
        float cn = gf * creg + gi * gg;
        float hn = go * tanhf(cn);
        float outv;
        if (m) { creg = cn; hreg = hn; outv = hn; } else { outv = 0.f; }

        outp[((size_t)(l * 64 + b0 + bb)) * 256 + h0 + hh] = outv;
        g_hbuf[dir][p ^ 1][(b0 + bb) * 256 + h0 + hh] = hreg;

        groupbar(gid);
        p ^= 1;
    }
}

// ---------------------------------------------------------------------------
// Kernel 3a: transpose W_out (T,512) -> g_WoutT (512,T).
// ---------------------------------------------------------------------------
__global__ void wtrans_kernel(const float* __restrict__ Wout) {
    int idx = blockIdx.x * 256 + threadIdx.x;
    if (idx < 512 * NT) {
        int k = idx >> 5, t = idx & 31;
        g_WoutT[idx] = Wout[t * 512 + k];
    }
}

// ---------------------------------------------------------------------------
// Kernel 3b: emissions = [h_f | h_b] @ W_out^T + b_out.
// 512 blocks x 8 tiles; W transposed to [t][514] in smem so both h and w
// give contiguous k-pairs -> FFMA2 with no packing.
// ---------------------------------------------------------------------------
#define WT_PAD 514
#define EMIS_SMEM_BYTES ((32 * WT_PAD + 8 * 512) * 4)
__global__ __launch_bounds__(256) void emis_kernel(const float* __restrict__ bout)
{
    extern __shared__ float sm[];
    float* wsmT = sm;                   // [32 t][514]
    float* hsm  = sm + 32 * WT_PAD;     // [8 r][512]
    const int tid = threadIdx.x;
    const int r = tid >> 5, t = tid & 31;
    const float bb = bout[t];

    for (int i = 0; i < 64; i++) {
        int idx = tid + i * 256;                 // 0..16383
        int k = idx >> 5, tt = idx & 31;
        wsmT[tt * WT_PAD + k] = g_WoutT[idx];
    }

    for (int it = 0; it < 8; it++) {
        const int bm = blockIdx.x * 8 + it;      // 0..4095
        __syncthreads();
        for (int i = 0; i < 16; i++) {
            int idx = tid + i * 256;
            int rr = idx >> 9, k = idx & 511;
            size_t row = (size_t)bm * 8 + rr;
            hsm[idx] = (k < 256) ? g_hout[0][row * 256 + k]
                                 : g_hout[1][row * 256 + (k - 256)];
        }
        __syncthreads();

        const float* hr = hsm + r * 512;
        const float* wr = wsmT + t * WT_PAD;
        unsigned long long acc2 = 0ull;
#pragma unroll 8
        for (int k = 0; k < 512; k += 4) {
            ulonglong2 h2 = *(const ulonglong2*)(hr + k);
            unsigned long long w01 = *(const unsigned long long*)(wr + k);
            unsigned long long w23 = *(const unsigned long long*)(wr + k + 2);
            FMA2(acc2, h2.x, w01);
            FMA2(acc2, h2.y, w23);
        }
        float lo, hi;
        UNPK2(lo, hi, acc2);
        g_em[((size_t)bm * 8 + r) * 32 + t] = lo + hi + bb;
    }
}

// ---------------------------------------------------------------------------
// Kernel 4: CRF. One warp per batch (MUFU-latency floor; unchanged, proven).
// ---------------------------------------------------------------------------
__global__ __launch_bounds__(32) void crf_kernel(
    const int* __restrict__ tags, const int* __restrict__ masks,
    const float* __restrict__ start_trans, const float* __restrict__ end_trans,
    const float* __restrict__ trans)
{
    __shared__ float tsm[NT * NT];
    const int b = blockIdx.x;
    const int j = threadIdx.x;

    for (int i = j; i < NT * NT; i += 32) tsm[i] = trans[i];
    __syncwarp();

    float score = start_trans[j] + g_em[(size_t)b * 32 + j];
    for (int l = 1; l < 512; l++) {
        float e = g_em[((size_t)(l * 64 + b)) * 32 + j];
        int   m = masks[l * 64 + b];
        float v[32];
        float mx = -3.4e38f;
#pragma unroll
        for (int i = 0; i < 32; i++) {
            v[i] = __shfl_sync(0xffffffffu, score, i) + tsm[i * 32 + j];
            mx = fmaxf(mx, v[i]);
        }
        float s = 0.f;
#pragma unroll
        for (int i = 0; i < 32; i++) s += __expf(v[i] - mx);
        float nxt = mx + __logf(s) + e;
        score = m ? nxt : score;
    }

    float part = 0.f;
    int lenp = 0;
    for (int l = j; l < 512; l += 32) {
        int m = masks[l * 64 + b];
        lenp += m;
        int tg = tags[l * 64 + b];
        float e = g_em[((size_t)(l * 64 + b)) * 32 + tg];
        if (l == 0) {
            part += start_trans[tg] + e;
        } else {
            int tp = tags[(l - 1) * 64 + b];
            part += (e + tsm[tp * 32 + tg]) * (float)m;
        }
    }
#pragma unroll
    for (int off = 16; off > 0; off >>= 1) {
        part += __shfl_xor_sync(0xffffffffu, part, off);
        lenp += __shfl_xor_sync(0xffffffffu, lenp, off);
    }

    float tv = score + end_trans[j];
    float mx = tv;
#pragma unroll
    for (int off = 16; off > 0; off >>= 1)
        mx = fmaxf(mx, __shfl_xor_sync(0xffffffffu, mx, off));
    float ex = __expf(tv - mx);
#pragma unroll
    for (int off = 16; off > 0; off >>= 1)
        ex += __shfl_xor_sync(0xffffffffu, ex, off);
    float logz = mx + __logf(ex);

    if (j == 0) {
        int last = tags[(lenp - 1) * 64 + b];
        float num = part + end_trans[last];
        g_llh[b] = num - logz;
    }
}

// ---------------------------------------------------------------------------
// Kernel 5: out = -mean(llh)
// ---------------------------------------------------------------------------
__global__ void final_kernel(float* __restrict__ out) {
    if (threadIdx.x == 0) {
        float s = 0.f;
        for (int i = 0; i < NB; i++) s += g_llh[i];
        out[0] = -s / (float)NB;
    }
}

// ---------------------------------------------------------------------------
extern "C" void kernel_launch(void* const* d_in, const int* in_sizes, int n_in,
                              void* d_out, int out_size) {
    const int*   seqs        = (const int*)d_in[0];
    const int*   tags        = (const int*)d_in[1];
    const int*   masks       = (const int*)d_in[2];
    const float* embed       = (const float*)d_in[3];
    const float* W_ih_f      = (const float*)d_in[4];
    const float* W_hh_f      = (const float*)d_in[5];
    const float* b_ih_f      = (const float*)d_in[6];
    const float* b_hh_f      = (const float*)d_in[7];
    const float* W_ih_b      = (const float*)d_in[8];
    const float* W_hh_b      = (const float*)d_in[9];
    const float* b_ih_b      = (const float*)d_in[10];
    const float* b_hh_b      = (const float*)d_in[11];
    const float* W_out       = (const float*)d_in[12];
    const float* b_out       = (const float*)d_in[13];
    const float* start_trans = (const float*)d_in[14];
    const float* end_trans   = (const float*)d_in[15];
    const float* trans       = (const float*)d_in[16];

    cudaFuncSetAttribute(lstm_kernel, cudaFuncAttributeMaxDynamicSharedMemorySize,
                         LSTM_SMEM_BYTES);
    cudaFuncSetAttribute(emis_kernel, cudaFuncAttributeMaxDynamicSharedMemorySize,
                         EMIS_SMEM_BYTES);

    dim3 xg(16, 512, 2);
    xproj_kernel<<<xg, 256>>>(embed, seqs, W_ih_f, W_ih_b,
                              b_ih_f, b_hh_f, b_ih_b, b_hh_b);
    wtrans_kernel<<<64, 256>>>(W_out);
    lstm_kernel<<<128, 256, LSTM_SMEM_BYTES>>>(W_hh_f, W_hh_b, masks);
    emis_kernel<<<512, 256, EMIS_SMEM_BYTES>>>(b_out);
    crf_kernel<<<64, 32>>>(tags, masks, start_trans, end_trans, trans);
    final_kernel<<<1, 32>>>((float*)d_out);
}

// round 11
// speedup vs baseline: 1.1403x; 1.1403x over previous
#include <cuda_runtime.h>
#include <cuda_bf16.h>

// Problem dims
#define SL 512   // sequence length L
#define NB 64    // batch
#define NE 256   // embed dim E
#define NH 256   // hidden H
#define NG 1024  // 4*H
#define NT 32    // tags T

// ---------------------------------------------------------------------------
// Packed f32x2 helpers
// ---------------------------------------------------------------------------
#define FMA2(acc, a, b) \
    asm("fma.rn.f32x2 %0, %1, %2, %0;" : "+l"(acc) : "l"(a), "l"(b))
#define ADD2(acc, v) \
    asm("add.rn.f32x2 %0, %0, %1;" : "+l"(acc) : "l"(v))
#define DUP2(d, s) do { unsigned _u = __float_as_uint(s); \
    asm("mov.b64 %0, {%1, %1};" : "=l"(d) : "r"(_u)); } while (0)
#define UNPK2(lo, hi, v) do { unsigned _a, _b; \
    asm("mov.b64 {%0, %1}, %2;" : "=r"(_a), "=r"(_b) : "l"(v)); \
    lo = __uint_as_float(_a); hi = __uint_as_float(_b); } while (0)

// ---------------------------------------------------------------------------
// Device-global scratch
// ---------------------------------------------------------------------------
__device__ float    g_xproj[2][(size_t)SL * NB * NG];
__device__ float    g_hout [2][(size_t)SL * NB * NH];
__device__ float    g_em   [(size_t)SL * NB * NT];
__device__ float    g_hbuf [2][2][NB * NH];
__device__ float    g_WoutT[512 * NT];
__device__ float    g_llh  [NB];
__device__ unsigned g_gcnt[16 * 32];
__device__ unsigned g_ggen[16 * 32];

// ---------------------------------------------------------------------------
// 16-block group barrier (generation-relative; safe across graph replays)
// ---------------------------------------------------------------------------
__device__ __forceinline__ void groupbar(int gid) {
    __threadfence();
    __syncthreads();
    if (threadIdx.x == 0) {
        volatile unsigned* vgen = &g_ggen[gid * 32];
        unsigned gen = *vgen;
        unsigned t = atomicAdd(&g_gcnt[gid * 32], 1u);
        if (t == 15u) {
            g_gcnt[gid * 32] = 0u;
            __threadfence();
            *vgen = gen + 1u;
        } else {
            while (*vgen == gen) { }
        }
        __threadfence();
    }
    __syncthreads();
}

// ---------------------------------------------------------------------------
// Kernel 1: x_proj = gather(embed, seqs) @ W_ih^T + (b_ih + b_hh)
// 128x128x16 tile, 256 thr, 8x8 microtile, FFMA2 over natural row-pairs.
// grid = (8, 256, 2)
// ---------------------------------------------------------------------------
__global__ __launch_bounds__(256) void xproj_kernel(
    const float* __restrict__ embed, const int* __restrict__ seqs,
    const float* __restrict__ Wf, const float* __restrict__ Wb,
    const float* __restrict__ bihf, const float* __restrict__ bhhf,
    const float* __restrict__ bihb, const float* __restrict__ bhhb)
{
    __shared__ float As[16][128];
    __shared__ float Bs[16][128];

    const int dir = blockIdx.z;
    const float* W  = dir ? Wb   : Wf;
    const float* b1 = dir ? bihb : bihf;
    const float* b2 = dir ? bhhb : bhhf;
    float* out = g_xproj[dir];

    const int tid = threadIdx.x;
    const int bn = blockIdx.x;          // 0..7
    const int bm = blockIdx.y;          // 0..255
    const int tx = tid & 15;            // col octet
    const int ty = tid >> 4;            // row octet
    const int lr = tid & 127;           // load row
    const int kc = tid >> 7;            // 0..1

    const long arow = (long)seqs[bm * 128 + lr] * 256;
    const float* Brow = W + (long)(bn * 128 + lr) * 256;

    unsigned long long acc2[4][8];      // [row-pair][col]
#pragma unroll
    for (int i = 0; i < 4; i++)
#pragma unroll
        for (int j = 0; j < 8; j++) acc2[i][j] = 0ull;

    for (int k0 = 0; k0 < 256; k0 += 16) {
        float4 a0 = *(const float4*)(embed + arow + k0 + kc * 4);
        float4 a1 = *(const float4*)(embed + arow + k0 + (kc + 2) * 4);
        float4 c0 = *(const float4*)(Brow + k0 + kc * 4);
        float4 c1 = *(const float4*)(Brow + k0 + (kc + 2) * 4);
        __syncthreads();
        As[kc*4 + 0][lr] = a0.x; As[kc*4 + 1][lr] = a0.y;
        As[kc*4 + 2][lr] = a0.z; As[kc*4 + 3][lr] = a0.w;
        As[(kc+2)*4 + 0][lr] = a1.x; As[(kc+2)*4 + 1][lr] = a1.y;
        As[(kc+2)*4 + 2][lr] = a1.z; As[(kc+2)*4 + 3][lr] = a1.w;
        Bs[kc*4 + 0][lr] = c0.x; Bs[kc*4 + 1][lr] = c0.y;
        Bs[kc*4 + 2][lr] = c0.z; Bs[kc*4 + 3][lr] = c0.w;
        Bs[(kc+2)*4 + 0][lr] = c1.x; Bs[(kc+2)*4 + 1][lr] = c1.y;
        Bs[(kc+2)*4 + 2][lr] = c1.z; Bs[(kc+2)*4 + 3][lr] = c1.w;
        __syncthreads();
#pragma unroll
        for (int k = 0; k < 16; k++) {
            ulonglong2 ap0 = *(const ulonglong2*)&As[k][ty * 8];
            ulonglong2 ap1 = *(const ulonglong2*)&As[k][ty * 8 + 4];
            float4 bv0 = *(const float4*)&Bs[k][tx * 8];
            float4 bv1 = *(const float4*)&Bs[k][tx * 8 + 4];
            unsigned long long bd[8];
            DUP2(bd[0], bv0.x); DUP2(bd[1], bv0.y);
            DUP2(bd[2], bv0.z); DUP2(bd[3], bv0.w);
            DUP2(bd[4], bv1.x); DUP2(bd[5], bv1.y);
            DUP2(bd[6], bv1.z); DUP2(bd[7], bv1.w);
            unsigned long long ap[4] = {ap0.x, ap0.y, ap1.x, ap1.y};
#pragma unroll
            for (int ip = 0; ip < 4; ip++)
#pragma unroll
                for (int j = 0; j < 8; j++)
                    FMA2(acc2[ip][j], ap[ip], bd[j]);
        }
    }

    const int ng = bn * 128 + tx * 8;
    float bias[8];
#pragma unroll
    for (int j = 0; j < 8; j++) bias[j] = b1[ng + j] + b2[ng + j];

    float o[8][8];
#pragma unroll
    for (int ip = 0; ip < 4; ip++)
#pragma unroll
        for (int j = 0; j < 8; j++) {
            float lo, hi;
            UNPK2(lo, hi, acc2[ip][j]);
            o[2*ip][j]   = lo + bias[j];
            o[2*ip+1][j] = hi + bias[j];
        }
#pragma unroll
    for (int i = 0; i < 8; i++) {
        long r = (long)bm * 128 + ty * 8 + i;
        *(float4*)(out + r * 1024 + ng)     = make_float4(o[i][0], o[i][1], o[i][2], o[i][3]);
        *(float4*)(out + r * 1024 + ng + 4) = make_float4(o[i][4], o[i][5], o[i][6], o[i][7]);
    }
}

// ---------------------------------------------------------------------------
// Kernel 2: persistent BiLSTM. 256 blocks x 128 thr; 2 blocks/SM from
// different barrier groups (overlap compute vs spin). Block = 8 batch x 16
// hidden. W_hh held in REGISTERS (128 floats/thread) — no per-step smem W
// traffic. 16-block group barrier per (dir, batch-octet).
// ---------------------------------------------------------------------------
__global__ __launch_bounds__(128, 2) void lstm_kernel(
    const float* __restrict__ Whhf, const float* __restrict__ Whhb,
    const int* __restrict__ masks)
{
    __shared__ float hsm[8 * 256];                 // h_prev stage (8KB)
    __shared__ unsigned long long psum[4096];      // [ks][g][b][hh] (32KB)

    const int tid  = threadIdx.x;
    const int lane = tid & 31;
    const int w    = tid >> 5;
    const int bid  = blockIdx.x;
    const int grp  = bid & 15;           // barrier group
    const int dir  = grp >> 3;
    const int b0   = (grp & 7) * 8;      // batch octet
    const int h0   = (bid >> 4) * 16;    // hidden chunk (0..15 -> *16)
    const int hh   = lane & 15;          // GEMM-phase hidden idx
    const int ks   = w * 2 + (lane >> 4);// GEMM-phase k-slice (0..7, 32 k each)
    const int bb   = tid >> 4;           // update-phase batch idx (0..7)
    const int hh2  = tid & 15;           // update-phase hidden idx

    const float* W  = dir ? Whhb : Whhf;
    const float* xp = g_xproj[dir];
    float* outp = g_hout[dir];

    // One-time: W chunk into registers. wr[g][u] = packed (k, k+1) pair.
    unsigned long long wr[4][16];
#pragma unroll
    for (int g = 0; g < 4; g++) {
        const float* wp = W + ((size_t)(g * 256 + h0 + hh)) * 256 + ks * 32;
#pragma unroll
        for (int u = 0; u < 16; u++)
            wr[g][u] = *(const unsigned long long*)(wp + u * 2);
    }

    g_hbuf[dir][0][(b0 + bb) * 256 + h0 + hh2] = 0.f;
    float hreg = 0.f, creg = 0.f;
    groupbar(grp);

    float4* hsm4 = (float4*)hsm;
    const ulonglong2* hU2 = (const ulonglong2*)hsm;  // [8][64]

    int p = 0;
    for (int step = 0; step < 512; step++) {
        const int l = dir ? (511 - step) : step;

        // Prefetch gate pre-activations + mask (independent of barrier).
        const float* xr = xp + ((size_t)(l * 64 + b0 + bb)) * 1024 + h0 + hh2;
        float x0 = __ldg(xr + 0);
        float x1 = __ldg(xr + 256);
        float x2 = __ldg(xr + 512);
        float x3 = __ldg(xr + 768);
        int   m  = __ldg(masks + l * 64 + b0 + bb);

        // Stage h_prev (8 x 256) from L2.
        const float4* hb4 = (const float4*)g_hbuf[dir][p];
#pragma unroll
        for (int i = 0; i < 4; i++) {
            int idx = tid + i * 128;     // 0..511
            hsm4[idx] = __ldcg(hb4 + (b0 + (idx >> 6)) * 64 + (idx & 63));
        }
        __syncthreads();

        // GEMM from registers: 2 passes of 4 batches (caps reg pressure).
#pragma unroll
        for (int pass = 0; pass < 2; pass++) {
            unsigned long long acc[4][4];
#pragma unroll
            for (int g = 0; g < 4; g++)
#pragma unroll
                for (int b = 0; b < 4; b++) acc[g][b] = 0ull;
#pragma unroll
            for (int b = 0; b < 4; b++) {
                const ulonglong2* hp = hU2 + (pass * 4 + b) * 64 + ks * 8;
#pragma unroll
                for (int u2 = 0; u2 < 8; u2++) {
                    ulonglong2 hv = hp[u2];
                    FMA2(acc[0][b], wr[0][2*u2], hv.x);
                    FMA2(acc[0][b], wr[0][2*u2+1], hv.y);
                    FMA2(acc[1][b], wr[1][2*u2], hv.x);
                    FMA2(acc[1][b], wr[1][2*u2+1], hv.y);
                    FMA2(acc[2][b], wr[2][2*u2], hv.x);
                    FMA2(acc[2][b], wr[2][2*u2+1], hv.y);
                    FMA2(acc[3][b], wr[3][2*u2], hv.x);
                    FMA2(acc[3][b], wr[3][2*u2+1], hv.y);
                }
            }
#pragma unroll
            for (int g = 0; g < 4; g++)
#pragma unroll
                for (int b = 0; b < 4; b++)
                    psum[((ks * 4 + g) * 8 + pass * 4 + b) * 16 + hh] = acc[g][b];
        }
        __syncthreads();

        // Reduce across the 8 k-slices; thread = (bb, hh2).
        unsigned long long s0 = 0ull, s1 = 0ull, s2 = 0ull, s3 = 0ull;
#pragma unroll
        for (int k2 = 0; k2 < 8; k2++) {
            ADD2(s0, psum[((k2 * 4 + 0) * 8 + bb) * 16 + hh2]);
            ADD2(s1, psum[((k2 * 4 + 1) * 8 + bb) * 16 + hh2]);
            ADD2(s2, psum[((k2 * 4 + 2) * 8 + bb) * 16 + hh2]);
            ADD2(s3, psum[((k2 * 4 + 3) * 8 + bb) * 16 + hh2]);
        }
        float lo, hi, f0, f1, f2, f3;
        UNPK2(lo, hi, s0); f0 = lo + hi;
        UNPK2(lo, hi, s1); f1 = lo + hi;
        UNPK2(lo, hi, s2); f2 = lo + hi;
        UNPK2(lo, hi, s3); f3 = lo + hi;

        float gi = 1.f / (1.f + __expf(-(x0 + f0)));
        float gf = 1.f / (1.f + __expf(-(x1 + f1)));
        float gg = tanhf(x2 + f2);
        float go = 1.f / (1.f + __expf(-(x3 + f3)));
        float cn = gf * creg + gi * gg;
        float hn = go * tanhf(cn);
        float outv;
        if (m) { creg = cn; hreg = hn; outv = hn; } else { outv = 0.f; }

        outp[((size_t)(l * 64 + b0 + bb)) * 256 + h0 + hh2] = outv;
        g_hbuf[dir][p ^ 1][(b0 + bb) * 256 + h0 + hh2] = hreg;

        groupbar(grp);
        p ^= 1;
    }
}

// ---------------------------------------------------------------------------
// Kernel 3a: transpose W_out (T,512) -> g_WoutT (512,T).
// ---------------------------------------------------------------------------
__global__ void wtrans_kernel(const float* __restrict__ Wout) {
    int idx = blockIdx.x * 256 + threadIdx.x;
    if (idx < 512 * NT) {
        int k = idx >> 5, t = idx & 31;
        g_WoutT[idx] = Wout[t * 512 + k];
    }
}

// ---------------------------------------------------------------------------
// Kernel 3b: emissions = [h_f | h_b] @ W_out^T + b_out.
// ---------------------------------------------------------------------------
#define WT_PAD 514
#define EMIS_SMEM_BYTES ((32 * WT_PAD + 8 * 512) * 4)
__global__ __launch_bounds__(256) void emis_kernel(const float* __restrict__ bout)
{
    extern __shared__ float sm[];
    float* wsmT = sm;                   // [32 t][514]
    float* hsm  = sm + 32 * WT_PAD;     // [8 r][512]
    const int tid = threadIdx.x;
    const int r = tid >> 5, t = tid & 31;
    const float bb = bout[t];

    for (int i = 0; i < 64; i++) {
        int idx = tid + i * 256;
        int k = idx >> 5, tt = idx & 31;
        wsmT[tt * WT_PAD + k] = g_WoutT[idx];
    }

    for (int it = 0; it < 8; it++) {
        const int bm = blockIdx.x * 8 + it;
        __syncthreads();
        for (int i = 0; i < 16; i++) {
            int idx = tid + i * 256;
            int rr = idx >> 9, k = idx & 511;
            size_t row = (size_t)bm * 8 + rr;
            hsm[idx] = (k < 256) ? g_hout[0][row * 256 + k]
                                 : g_hout[1][row * 256 + (k - 256)];
        }
        __syncthreads();

        const float* hr = hsm + r * 512;
        const float* wr = wsmT + t * WT_PAD;
        unsigned long long acc2 = 0ull;
#pragma unroll 8
        for (int k = 0; k < 512; k += 4) {
            ulonglong2 h2 = *(const ulonglong2*)(hr + k);
            unsigned long long w01 = *(const unsigned long long*)(wr + k);
            unsigned long long w23 = *(const unsigned long long*)(wr + k + 2);
            FMA2(acc2, h2.x, w01);
            FMA2(acc2, h2.y, w23);
        }
        float lo, hi;
        UNPK2(lo, hi, acc2);
        g_em[((size_t)bm * 8 + r) * 32 + t] = lo + hi + bb;
    }
}

// ---------------------------------------------------------------------------
// Kernel 4: CRF. One warp per batch.
// ---------------------------------------------------------------------------
__global__ __launch_bounds__(32) void crf_kernel(
    const int* __restrict__ tags, const int* __restrict__ masks,
    const float* __restrict__ start_trans, const float* __restrict__ end_trans,
    const float* __restrict__ trans)
{
    __shared__ float tsm[NT * NT];
    const int b = blockIdx.x;
    const int j = threadIdx.x;

    for (int i = j; i < NT * NT; i += 32) tsm[i] = trans[i];
    __syncwarp();

    float score = start_trans[j] + g_em[(size_t)b * 32 + j];
    for (int l = 1; l < 512; l++) {
        float e = g_em[((size_t)(l * 64 + b)) * 32 + j];
        int   m = masks[l * 64 + b];
        float v[32];
        float mx = -3.4e38f;
#pragma unroll
        for (int i = 0; i < 32; i++) {
            v[i] = __shfl_sync(0xffffffffu, score, i) + tsm[i * 32 + j];
            mx = fmaxf(mx, v[i]);
        }
        float s = 0.f;
#pragma unroll
        for (int i = 0; i < 32; i++) s += __expf(v[i] - mx);
        float nxt = mx + __logf(s) + e;
        score = m ? nxt : score;
    }

    float part = 0.f;
    int lenp = 0;
    for (int l = j; l < 512; l += 32) {
        int m = masks[l * 64 + b];
        lenp += m;
        int tg = tags[l * 64 + b];
        float e = g_em[((size_t)(l * 64 + b)) * 32 + tg];
        if (l == 0) {
            part += start_trans[tg] + e;
        } else {
            int tp = tags[(l - 1) * 64 + b];
            part += (e + tsm[tp * 32 + tg]) * (float)m;
        }
    }
#pragma unroll
    for (int off = 16; off > 0; off >>= 1) {
        part += __shfl_xor_sync(0xffffffffu, part, off);
        lenp += __shfl_xor_sync(0xffffffffu, lenp, off);
    }

    float tv = score + end_trans[j];
    float mx = tv;
#pragma unroll
    for (int off = 16; off > 0; off >>= 1)
        mx = fmaxf(mx, __shfl_xor_sync(0xffffffffu, mx, off));
    float ex = __expf(tv - mx);
#pragma unroll
    for (int off = 16; off > 0; off >>= 1)
        ex += __shfl_xor_sync(0xffffffffu, ex, off);
    float logz = mx + __logf(ex);

    if (j == 0) {
        int last = tags[(lenp - 1) * 64 + b];
        float num = part + end_trans[last];
        g_llh[b] = num - logz;
    }
}

// ---------------------------------------------------------------------------
// Kernel 5: out = -mean(llh)
// ---------------------------------------------------------------------------
__global__ void final_kernel(float* __restrict__ out) {
    if (threadIdx.x == 0) {
        float s = 0.f;
        for (int i = 0; i < NB; i++) s += g_llh[i];
        out[0] = -s / (float)NB;
    }
}

// ---------------------------------------------------------------------------
extern "C" void kernel_launch(void* const* d_in, const int* in_sizes, int n_in,
                              void* d_out, int out_size) {
    const int*   seqs        = (const int*)d_in[0];
    const int*   tags        = (const int*)d_in[1];
    const int*   masks       = (const int*)d_in[2];
    const float* embed       = (const float*)d_in[3];
    const float* W_ih_f      = (const float*)d_in[4];
    const float* W_hh_f      = (const float*)d_in[5];
    const float* b_ih_f      = (const float*)d_in[6];
    const float* b_hh_f      = (const float*)d_in[7];
    const float* W_ih_b      = (const float*)d_in[8];
    const float* W_hh_b      = (const float*)d_in[9];
    const float* b_ih_b      = (const float*)d_in[10];
    const float* b_hh_b      = (const float*)d_in[11];
    const float* W_out       = (const float*)d_in[12];
    const float* b_out       = (const float*)d_in[13];
    const float* start_trans = (const float*)d_in[14];
    const float* end_trans   = (const float*)d_in[15];
    const float* trans       = (const float*)d_in[16];

    cudaFuncSetAttribute(emis_kernel, cudaFuncAttributeMaxDynamicSharedMemorySize,
                         EMIS_SMEM_BYTES);

    dim3 xg(8, 256, 2);
    xproj_kernel<<<xg, 256>>>(embed, seqs, W_ih_f, W_ih_b,
                              b_ih_f, b_hh_f, b_ih_b, b_hh_b);
    wtrans_kernel<<<64, 256>>>(W_out);
    lstm_kernel<<<256, 128>>>(W_hh_f, W_hh_b, masks);
    emis_kernel<<<512, 256, EMIS_SMEM_BYTES>>>(b_out);
    crf_kernel<<<64, 32>>>(tags, masks, start_trans, end_trans, trans);
    final_kernel<<<1, 32>>>((float*)d_out);
}

// round 12
// speedup vs baseline: 1.1474x; 1.0062x over previous
#include <cuda_runtime.h>
#include <cuda_bf16.h>

// Problem dims
#define SL 512   // sequence length L
#define NB 64    // batch
#define NE 256   // embed dim E
#define NH 256   // hidden H
#define NG 1024  // 4*H
#define NT 32    // tags T

// ---------------------------------------------------------------------------
// Packed f32x2 helpers
// ---------------------------------------------------------------------------
#define FMA2(acc, a, b) \
    asm("fma.rn.f32x2 %0, %1, %2, %0;" : "+l"(acc) : "l"(a), "l"(b))
#define ADD2(acc, v) \
    asm("add.rn.f32x2 %0, %0, %1;" : "+l"(acc) : "l"(v))
#define DUP2(d, s) do { unsigned _u = __float_as_uint(s); \
    asm("mov.b64 %0, {%1, %1};" : "=l"(d) : "r"(_u)); } while (0)
#define UNPK2(lo, hi, v) do { unsigned _a, _b; \
    asm("mov.b64 {%0, %1}, %2;" : "=r"(_a), "=r"(_b) : "l"(v)); \
    lo = __uint_as_float(_a); hi = __uint_as_float(_b); } while (0)

// ---------------------------------------------------------------------------
// Device-global scratch
// ---------------------------------------------------------------------------
// x_proj stored GATE-LAST: [dir][l][b][h][g] so the LSTM reads one float4.
__device__ float    g_xproj[2][(size_t)SL * NB * NG];
__device__ float    g_hout [2][(size_t)SL * NB * NH];
__device__ float    g_em   [(size_t)SL * NB * NT];
__device__ float    g_hbuf [2][2][NB * NH];
__device__ float    g_WoutT[512 * NT];
__device__ float    g_llh  [NB];
__device__ unsigned g_gcnt[16 * 32];
__device__ unsigned g_ggen[16 * 32];

// ---------------------------------------------------------------------------
// 16-block group barrier (unchanged — proven across R8-R10)
// ---------------------------------------------------------------------------
__device__ __forceinline__ void groupbar(int gid) {
    __threadfence();
    __syncthreads();
    if (threadIdx.x == 0) {
        volatile unsigned* vgen = &g_ggen[gid * 32];
        unsigned gen = *vgen;
        unsigned t = atomicAdd(&g_gcnt[gid * 32], 1u);
        if (t == 15u) {
            g_gcnt[gid * 32] = 0u;
            __threadfence();
            *vgen = gen + 1u;
        } else {
            while (*vgen == gen) { }
        }
        __threadfence();
    }
    __syncthreads();
}

// ---------------------------------------------------------------------------
// Kernel 1: x_proj = gather(embed, seqs) @ W_ih^T + (b_ih + b_hh)
// Output column n encodes (h, g): n = h*4 + g  (gate-last). Achieved purely
// by permuting which W row / bias element each output column uses.
// 128x128x16 tile, 256 thr, 8x8 microtile, FFMA2. grid = (8, 256, 2)
// ---------------------------------------------------------------------------
__global__ __launch_bounds__(256) void xproj_kernel(
    const float* __restrict__ embed, const int* __restrict__ seqs,
    const float* __restrict__ Wf, const float* __restrict__ Wb,
    const float* __restrict__ bihf, const float* __restrict__ bhhf,
    const float* __restrict__ bihb, const float* __restrict__ bhhb)
{
    __shared__ float As[16][128];
    __shared__ float Bs[16][128];

    const int dir = blockIdx.z;
    const float* W  = dir ? Wb   : Wf;
    const float* b1 = dir ? bihb : bihf;
    const float* b2 = dir ? bhhb : bhhf;
    float* out = g_xproj[dir];

    const int tid = threadIdx.x;
    const int bn = blockIdx.x;          // 0..7
    const int bm = blockIdx.y;          // 0..255
    const int tx = tid & 15;
    const int ty = tid >> 4;
    const int lr = tid & 127;
    const int kc = tid >> 7;            // 0..1

    const long arow = (long)seqs[bm * 128 + lr] * 256;
    // Column n = bn*128 + lr -> W row = (n&3)*256 + (n>>2)  (gate-last perm)
    const int ncol = bn * 128 + lr;
    const float* Brow = W + (long)((ncol & 3) * 256 + (ncol >> 2)) * 256;

    unsigned long long acc2[4][8];
#pragma unroll
    for (int i = 0; i < 4; i++)
#pragma unroll
        for (int j = 0; j < 8; j++) acc2[i][j] = 0ull;

    for (int k0 = 0; k0 < 256; k0 += 16) {
        float4 a0 = *(const float4*)(embed + arow + k0 + kc * 4);
        float4 a1 = *(const float4*)(embed + arow + k0 + (kc + 2) * 4);
        float4 c0 = *(const float4*)(Brow + k0 + kc * 4);
        float4 c1 = *(const float4*)(Brow + k0 + (kc + 2) * 4);
        __syncthreads();
        As[kc*4 + 0][lr] = a0.x; As[kc*4 + 1][lr] = a0.y;
        As[kc*4 + 2][lr] = a0.z; As[kc*4 + 3][lr] = a0.w;
        As[(kc+2)*4 + 0][lr] = a1.x; As[(kc+2)*4 + 1][lr] = a1.y;
        As[(kc+2)*4 + 2][lr] = a1.z; As[(kc+2)*4 + 3][lr] = a1.w;
        Bs[kc*4 + 0][lr] = c0.x; Bs[kc*4 + 1][lr] = c0.y;
        Bs[kc*4 + 2][lr] = c0.z; Bs[kc*4 + 3][lr] = c0.w;
        Bs[(kc+2)*4 + 0][lr] = c1.x; Bs[(kc+2)*4 + 1][lr] = c1.y;
        Bs[(kc+2)*4 + 2][lr] = c1.z; Bs[(kc+2)*4 + 3][lr] = c1.w;
        __syncthreads();
#pragma unroll
        for (int k = 0; k < 16; k++) {
            ulonglong2 ap0 = *(const ulonglong2*)&As[k][ty * 8];
            ulonglong2 ap1 = *(const ulonglong2*)&As[k][ty * 8 + 4];
            float4 bv0 = *(const float4*)&Bs[k][tx * 8];
            float4 bv1 = *(const float4*)&Bs[k][tx * 8 + 4];
            unsigned long long bd[8];
            DUP2(bd[0], bv0.x); DUP2(bd[1], bv0.y);
            DUP2(bd[2], bv0.z); DUP2(bd[3], bv0.w);
            DUP2(bd[4], bv1.x); DUP2(bd[5], bv1.y);
            DUP2(bd[6], bv1.z); DUP2(bd[7], bv1.w);
            unsigned long long ap[4] = {ap0.x, ap0.y, ap1.x, ap1.y};
#pragma unroll
            for (int ip = 0; ip < 4; ip++)
#pragma unroll
                for (int j = 0; j < 8; j++)
                    FMA2(acc2[ip][j], ap[ip], bd[j]);
        }
    }

    const int ng = bn * 128 + tx * 8;
    float bias[8];
#pragma unroll
    for (int j = 0; j < 8; j++) {
        int n = ng + j;
        int wrow = (n & 3) * 256 + (n >> 2);
        bias[j] = b1[wrow] + b2[wrow];
    }

    float o[8][8];
#pragma unroll
    for (int ip = 0; ip < 4; ip++)
#pragma unroll
        for (int j = 0; j < 8; j++) {
            float lo, hi;
            UNPK2(lo, hi, acc2[ip][j]);
            o[2*ip][j]   = lo + bias[j];
            o[2*ip+1][j] = hi + bias[j];
        }
#pragma unroll
    for (int i = 0; i < 8; i++) {
        long r = (long)bm * 128 + ty * 8 + i;
        *(float4*)(out + r * 1024 + ng)     = make_float4(o[i][0], o[i][1], o[i][2], o[i][3]);
        *(float4*)(out + r * 1024 + ng + 4) = make_float4(o[i][4], o[i][5], o[i][6], o[i][7]);
    }
}

// ---------------------------------------------------------------------------
// Kernel 2: persistent BiLSTM (R10 structure, W in regs, 256x128thr, 2/SM).
// Gate-last x_proj -> single LDG.128 prefetch per thread per step.
// ---------------------------------------------------------------------------
__global__ __launch_bounds__(128, 2) void lstm_kernel(
    const float* __restrict__ Whhf, const float* __restrict__ Whhb,
    const int* __restrict__ masks)
{
    __shared__ float hsm[8 * 256];
    __shared__ unsigned long long psum[4096];

    const int tid  = threadIdx.x;
    const int lane = tid & 31;
    const int w    = tid >> 5;
    const int bid  = blockIdx.x;
    const int grp  = bid & 15;
    const int dir  = grp >> 3;
    const int b0   = (grp & 7) * 8;
    const int h0   = (bid >> 4) * 16;
    const int hh   = lane & 15;
    const int ks   = w * 2 + (lane >> 4);
    const int bb   = tid >> 4;
    const int hh2  = tid & 15;

    const float* W  = dir ? Whhb : Whhf;
    const float* xp = g_xproj[dir];
    float* outp = g_hout[dir];

    unsigned long long wr[4][16];
#pragma unroll
    for (int g = 0; g < 4; g++) {
        const float* wp = W + ((size_t)(g * 256 + h0 + hh)) * 256 + ks * 32;
#pragma unroll
        for (int u = 0; u < 16; u++)
            wr[g][u] = *(const unsigned long long*)(wp + u * 2);
    }

    g_hbuf[dir][0][(b0 + bb) * 256 + h0 + hh2] = 0.f;
    float hreg = 0.f, creg = 0.f;
    groupbar(grp);

    float4* hsm4 = (float4*)hsm;
    const ulonglong2* hU2 = (const ulonglong2*)hsm;

    int p = 0;
    for (int step = 0; step < 512; step++) {
        const int l = dir ? (511 - step) : step;

        // Single coalesced 16B prefetch of the 4 gate pre-activations.
        const float4 x4 = __ldg((const float4*)(
            xp + ((size_t)(l * 64 + b0 + bb)) * 1024 + (h0 + hh2) * 4));
        int m = __ldg(masks + l * 64 + b0 + bb);

        const float4* hb4 = (const float4*)g_hbuf[dir][p];
#pragma unroll
        for (int i = 0; i < 4; i++) {
            int idx = tid + i * 128;
            hsm4[idx] = __ldcg(hb4 + (b0 + (idx >> 6)) * 64 + (idx & 63));
        }
        __syncthreads();

#pragma unroll
        for (int pass = 0; pass < 2; pass++) {
            unsigned long long acc[4][4];
#pragma unroll
            for (int g = 0; g < 4; g++)
#pragma unroll
                for (int b = 0; b < 4; b++) acc[g][b] = 0ull;
#pragma unroll
            for (int b = 0; b < 4; b++) {
                const ulonglong2* hp = hU2 + (pass * 4 + b) * 64 + ks * 8;
#pragma unroll
                for (int u2 = 0; u2 < 8; u2++) {
                    ulonglong2 hv = hp[u2];
                    FMA2(acc[0][b], wr[0][2*u2], hv.x);
                    FMA2(acc[0][b], wr[0][2*u2+1], hv.y);
                    FMA2(acc[1][b], wr[1][2*u2], hv.x);
                    FMA2(acc[1][b], wr[1][2*u2+1], hv.y);
                    FMA2(acc[2][b], wr[2][2*u2], hv.x);
                    FMA2(acc[2][b], wr[2][2*u2+1], hv.y);
                    FMA2(acc[3][b], wr[3][2*u2], hv.x);
                    FMA2(acc[3][b], wr[3][2*u2+1], hv.y);
                }
            }
#pragma unroll
            for (int g = 0; g < 4; g++)
#pragma unroll
                for (int b = 0; b < 4; b++)
                    psum[((ks * 4 + g) * 8 + pass * 4 + b) * 16 + hh] = acc[g][b];
        }
        __syncthreads();

        unsigned long long s0 = 0ull, s1 = 0ull, s2 = 0ull, s3 = 0ull;
#pragma unroll
        for (int k2 = 0; k2 < 8; k2++) {
            ADD2(s0, psum[((k2 * 4 + 0) * 8 + bb) * 16 + hh2]);
            ADD2(s1, psum[((k2 * 4 + 1) * 8 + bb) * 16 + hh2]);
            ADD2(s2, psum[((k2 * 4 + 2) * 8 + bb) * 16 + hh2]);
            ADD2(s3, psum[((k2 * 4 + 3) * 8 + bb) * 16 + hh2]);
        }
        float lo, hi, f0, f1, f2, f3;
        UNPK2(lo, hi, s0); f0 = lo + hi;
        UNPK2(lo, hi, s1); f1 = lo + hi;
        UNPK2(lo, hi, s2); f2 = lo + hi;
        UNPK2(lo, hi, s3); f3 = lo + hi;

        float gi = 1.f / (1.f + __expf(-(x4.x + f0)));
        float gf = 1.f / (1.f + __expf(-(x4.y + f1)));
        float gg = tanhf(x4.z + f2);
        float go = 1.f / (1.f + __expf(-(x4.w + f3)));
        float cn = gf * creg + gi * gg;
        float hn = go * tanhf(cn);
        float outv;
        if (m) { creg = cn; hreg = hn; outv = hn; } else { outv = 0.f; }

        outp[((size_t)(l * 64 + b0 + bb)) * 256 + h0 + hh2] = outv;
        g_hbuf[dir][p ^ 1][(b0 + bb) * 256 + h0 + hh2] = hreg;

        groupbar(grp);
        p ^= 1;
    }
}

// ---------------------------------------------------------------------------
// Kernel 3a: transpose W_out (T,512) -> g_WoutT (512,T).
// ---------------------------------------------------------------------------
__global__ void wtrans_kernel(const float* __restrict__ Wout) {
    int idx = blockIdx.x * 256 + threadIdx.x;
    if (idx < 512 * NT) {
        int k = idx >> 5, t = idx & 31;
        g_WoutT[idx] = Wout[t * 512 + k];
    }
}

// ---------------------------------------------------------------------------
// Kernel 3b: emissions. float4 staging (4x MLP) + 4 packed accumulators
// (4x ILP on the dot chain). 1024 blocks x 4 tiles.
// ---------------------------------------------------------------------------
#define WT_PAD 514
#define EMIS_SMEM_BYTES ((32 * WT_PAD + 8 * 512) * 4)
__global__ __launch_bounds__(256) void emis_kernel(const float* __restrict__ bout)
{
    extern __shared__ float sm[];
    float* wsmT = sm;                   // [32 t][514]
    float* hsm  = sm + 32 * WT_PAD;     // [8 r][512]
    float4* hsm4 = (float4*)hsm;
    const int tid = threadIdx.x;
    const int r = tid >> 5, t = tid & 31;
    const float bb = bout[t];

    for (int i = 0; i < 64; i++) {
        int idx = tid + i * 256;
        int k = idx >> 5, tt = idx & 31;
        wsmT[tt * WT_PAD + k] = g_WoutT[idx];
    }

    const float4* h0p = (const float4*)g_hout[0];
    const float4* h1p = (const float4*)g_hout[1];

    for (int it = 0; it < 4; it++) {
        const int bm = blockIdx.x * 4 + it;      // 0..4095
        __syncthreads();
#pragma unroll
        for (int i = 0; i < 4; i++) {
            int idx4 = tid + i * 256;            // 0..1023 float4 slots
            int rr = idx4 >> 7, c4 = idx4 & 127; // row, float4-col (512f = 128 f4)
            size_t row = (size_t)bm * 8 + rr;
            hsm4[idx4] = (c4 < 64) ? __ldg(h0p + row * 64 + c4)
                                   : __ldg(h1p + row * 64 + (c4 - 64));
        }
        __syncthreads();

        const float* hr = hsm + r * 512;
        const float* wr = wsmT + t * WT_PAD;
        unsigned long long a0 = 0ull, a1 = 0ull, a2 = 0ull, a3 = 0ull;
#pragma unroll 4
        for (int k = 0; k < 512; k += 16) {
            ulonglong2 hA = *(const ulonglong2*)(hr + k);
            ulonglong2 hB = *(const ulonglong2*)(hr + k + 4);
            ulonglong2 hC = *(const ulonglong2*)(hr + k + 8);
            ulonglong2 hD = *(const ulonglong2*)(hr + k + 12);
            FMA2(a0, hA.x, *(const unsigned long long*)(wr + k));
            FMA2(a0, hA.y, *(const unsigned long long*)(wr + k + 2));
            FMA2(a1, hB.x, *(const unsigned long long*)(wr + k + 4));
            FMA2(a1, hB.y, *(const unsigned long long*)(wr + k + 6));
            FMA2(a2, hC.x, *(const unsigned long long*)(wr + k + 8));
            FMA2(a2, hC.y, *(const unsigned long long*)(wr + k + 10));
            FMA2(a3, hD.x, *(const unsigned long long*)(wr + k + 12));
            FMA2(a3, hD.y, *(const unsigned long long*)(wr + k + 14));
        }
        ADD2(a0, a1); ADD2(a2, a3); ADD2(a0, a2);
        float lo, hi;
        UNPK2(lo, hi, a0);
        g_em[((size_t)bm * 8 + r) * 32 + t] = lo + hi + bb;
    }
}

// ---------------------------------------------------------------------------
// Kernel 4: CRF. 128 threads per batch: 4 warps split the inner-tag LSE
// (8 source tags each), warp 0 merges partials. Tail (numerator, log_z)
// computed by the whole block / warp 0.
// ---------------------------------------------------------------------------
__global__ __launch_bounds__(128) void crf_kernel(
    const int* __restrict__ tags, const int* __restrict__ masks,
    const float* __restrict__ start_trans, const float* __restrict__ end_trans,
    const float* __restrict__ trans)
{
    __shared__ float tsm[NT * NT];
    __shared__ float ssm[NT];
    __shared__ float pm[4][NT];
    __shared__ float ps[4][NT];
    __shared__ float redf[8];
    __shared__ int   redi[8];

    const int b = blockIdx.x;
    const int tid = threadIdx.x;
    const int w = tid >> 5;
    const int j = tid & 31;

    for (int i = tid; i < NT * NT; i += 128) tsm[i] = trans[i];
    if (w == 0) ssm[j] = start_trans[j] + g_em[(size_t)b * 32 + j];
    __syncthreads();

    for (int l = 1; l < 512; l++) {
        float v[8];
        float mx = -3.4e38f;
#pragma unroll
        for (int ii = 0; ii < 8; ii++) {
            int i = w * 8 + ii;
            v[ii] = ssm[i] + tsm[i * 32 + j];
            mx = fmaxf(mx, v[ii]);
        }
        float s = 0.f;
#pragma unroll
        for (int ii = 0; ii < 8; ii++) s += __expf(v[ii] - mx);
        pm[w][j] = mx;
        ps[w][j] = s;
        __syncthreads();
        if (w == 0) {
            float m0 = pm[0][j], m1 = pm[1][j], m2 = pm[2][j], m3 = pm[3][j];
            float M = fmaxf(fmaxf(m0, m1), fmaxf(m2, m3));
            float S = ps[0][j] * __expf(m0 - M) + ps[1][j] * __expf(m1 - M)
                    + ps[2][j] * __expf(m2 - M) + ps[3][j] * __expf(m3 - M);
            float nxt = M + __logf(S) + g_em[((size_t)(l * 64 + b)) * 32 + j];
            if (masks[l * 64 + b]) ssm[j] = nxt;
        }
        __syncthreads();
    }

    // Numerator + length, strided over all 128 threads.
    float part = 0.f;
    int lenp = 0;
    for (int l = tid; l < 512; l += 128) {
        int m = masks[l * 64 + b];
        lenp += m;
        int tg = tags[l * 64 + b];
        float e = g_em[((size_t)(l * 64 + b)) * 32 + tg];
        if (l == 0) {
            part += start_trans[tg] + e;
        } else {
            int tp = tags[(l - 1) * 64 + b];
            part += (e + tsm[tp * 32 + tg]) * (float)m;
        }
    }
#pragma unroll
    for (int off = 16; off > 0; off >>= 1) {
        part += __shfl_xor_sync(0xffffffffu, part, off);
        lenp += __shfl_xor_sync(0xffffffffu, lenp, off);
    }
    if (j == 0) { redf[w] = part; redi[w] = lenp; }
    __syncthreads();

    if (w == 0) {
        float num_p = redf[0] + redf[1] + redf[2] + redf[3];
        int   length = redi[0] + redi[1] + redi[2] + redi[3];

        float tv = ssm[j] + end_trans[j];
        float mx = tv;
#pragma unroll
        for (int off = 16; off > 0; off >>= 1)
            mx = fmaxf(mx, __shfl_xor_sync(0xffffffffu, mx, off));
        float ex = __expf(tv - mx);
#pragma unroll
        for (int off = 16; off > 0; off >>= 1)
            ex += __shfl_xor_sync(0xffffffffu, ex, off);
        float logz = mx + __logf(ex);

        if (j == 0) {
            int last = tags[(length - 1) * 64 + b];
            g_llh[b] = (num_p + end_trans[last]) - logz;
        }
    }
}

// ---------------------------------------------------------------------------
// Kernel 5: out = -mean(llh)
// ---------------------------------------------------------------------------
__global__ void final_kernel(float* __restrict__ out) {
    if (threadIdx.x == 0) {
        float s = 0.f;
        for (int i = 0; i < NB; i++) s += g_llh[i];
        out[0] = -s / (float)NB;
    }
}

// ---------------------------------------------------------------------------
extern "C" void kernel_launch(void* const* d_in, const int* in_sizes, int n_in,
                              void* d_out, int out_size) {
    const int*   seqs        = (const int*)d_in[0];
    const int*   tags        = (const int*)d_in[1];
    const int*   masks       = (const int*)d_in[2];
    const float* embed       = (const float*)d_in[3];
    const float* W_ih_f      = (const float*)d_in[4];
    const float* W_hh_f      = (const float*)d_in[5];
    const float* b_ih_f      = (const float*)d_in[6];
    const float* b_hh_f      = (const float*)d_in[7];
    const float* W_ih_b      = (const float*)d_in[8];
    const float* W_hh_b      = (const float*)d_in[9];
    const float* b_ih_b      = (const float*)d_in[10];
    const float* b_hh_b      = (const float*)d_in[11];
    const float* W_out       = (const float*)d_in[12];
    const float* b_out       = (const float*)d_in[13];
    const float* start_trans = (const float*)d_in[14];
    const float* end_trans   = (const float*)d_in[15];
    const float* trans       = (const float*)d_in[16];

    cudaFuncSetAttribute(emis_kernel, cudaFuncAttributeMaxDynamicSharedMemorySize,
                         EMIS_SMEM_BYTES);

    dim3 xg(8, 256, 2);
    xproj_kernel<<<xg, 256>>>(embed, seqs, W_ih_f, W_ih_b,
                              b_ih_f, b_hh_f, b_ih_b, b_hh_b);
    wtrans_kernel<<<64, 256>>>(W_out);
    lstm_kernel<<<256, 128>>>(W_hh_f, W_hh_b, masks);
    emis_kernel<<<1024, 256, EMIS_SMEM_BYTES>>>(b_out);
    crf_kernel<<<64, 128>>>(tags, masks, start_trans, end_trans, trans);
    final_kernel<<<1, 32>>>((float*)d_out);
}

// round 13
// speedup vs baseline: 1.1554x; 1.0070x over previous
#include <cuda_runtime.h>
#include <cuda_bf16.h>
#include <cuda_fp16.h>

// Problem dims
#define SL 512   // sequence length L
#define NB 64    // batch
#define NE 256   // embed dim E
#define NH 256   // hidden H
#define NG 1024  // 4*H
#define NT 32    // tags T

// ---------------------------------------------------------------------------
// Packed f32x2 helpers
// ---------------------------------------------------------------------------
#define FMA2(acc, a, b) \
    asm("fma.rn.f32x2 %0, %1, %2, %0;" : "+l"(acc) : "l"(a), "l"(b))
#define ADD2(acc, v) \
    asm("add.rn.f32x2 %0, %0, %1;" : "+l"(acc) : "l"(v))
#define DUP2(d, s) do { unsigned _u = __float_as_uint(s); \
    asm("mov.b64 %0, {%1, %1};" : "=l"(d) : "r"(_u)); } while (0)
#define UNPK2(lo, hi, v) do { unsigned _a, _b; \
    asm("mov.b64 {%0, %1}, %2;" : "=r"(_a), "=r"(_b) : "l"(v)); \
    lo = __uint_as_float(_a); hi = __uint_as_float(_b); } while (0)

// ---------------------------------------------------------------------------
// Device-global scratch.  x_proj and h_out are fp16 (the two giant streams);
// x_proj is GATE-LAST: [dir][l][b][h][g] so the LSTM reads 4 gates in 8B.
// ---------------------------------------------------------------------------
__device__ __half    g_xproj[2][(size_t)SL * NB * NG];
__device__ __half    g_hout [2][(size_t)SL * NB * NH];
__device__ float     g_em   [(size_t)SL * NB * NT];
__device__ float     g_hbuf [2][2][NB * NH];
__device__ float     g_WoutT[512 * NT];
__device__ float     g_llh  [NB];
__device__ unsigned  g_gcnt[16 * 32];
__device__ unsigned  g_ggen[16 * 32];

// ---------------------------------------------------------------------------
// Split-phase 16-block group barrier (generation counter is monotonic across
// graph replays; blocks capture gen0 at entry).
// ---------------------------------------------------------------------------
__device__ __forceinline__ void group_arrive(int gid) {
    __syncthreads();
    if (threadIdx.x == 0) {
        __threadfence();
        unsigned t = atomicAdd(&g_gcnt[gid * 32], 1u);
        if (t == 15u) {
            g_gcnt[gid * 32] = 0u;
            __threadfence();
            atomicAdd(&g_ggen[gid * 32], 1u);
        }
    }
}
__device__ __forceinline__ void group_wait(int gid, unsigned exp) {
    if (threadIdx.x == 0) {
        volatile unsigned* vgen = &g_ggen[gid * 32];
        while ((int)(*vgen - exp) < 0) { }
        __threadfence();
    }
    __syncthreads();
}

// ---------------------------------------------------------------------------
// Kernel 1: x_proj (A-stationary).  One block per 128-row M-tile per dir.
// Gathered embed tile lives in smem, k-major, XOR-swizzled (conflict-free
// stores AND aligned LDS.128 reads).  8 N-tiles computed per block.
// Output fp16, gate-last via W-row permutation.  grid = (256, 2).
// ---------------------------------------------------------------------------
#define XP_SMEM_BYTES ((256 * 128 + 16 * 128) * 4)   // 139264
__global__ __launch_bounds__(256) void xproj_kernel(
    const float* __restrict__ embed, const int* __restrict__ seqs,
    const float* __restrict__ Wf, const float* __restrict__ Wb,
    const float* __restrict__ bihf, const float* __restrict__ bhhf,
    const float* __restrict__ bihb, const float* __restrict__ bhhb)
{
    extern __shared__ float xsm[];
    float* As = xsm;             // [256 k][128 m], phys col = m ^ ((k&15)<<3)
    float* Bs = xsm + 32768;     // [16 k][128 n]

    const int dir = blockIdx.y;
    const float* W  = dir ? Wb   : Wf;
    const float* b1 = dir ? bihb : bihf;
    const float* b2 = dir ? bhhb : bhhf;
    __half* out = g_xproj[dir];

    const int tid = threadIdx.x;
    const int bm = blockIdx.x;          // 0..255
    const int tx = tid & 15;
    const int ty = tid >> 4;
    const int lr = tid & 127;
    const int kc = tid >> 7;            // 0..1

    // Stage A tile once: thread = (row lr, k-half kc).
    {
        const long arow = (long)seqs[bm * 128 + lr] * 256 + kc * 128;
        const float* src = embed + arow;
#pragma unroll
        for (int kk = 0; kk < 128; kk += 4) {
            float4 v = __ldg((const float4*)(src + kk));
            int k = kc * 128 + kk;
            As[(k + 0) * 128 + (lr ^ (((k + 0) & 15) << 3))] = v.x;
            As[(k + 1) * 128 + (lr ^ (((k + 1) & 15) << 3))] = v.y;
            As[(k + 2) * 128 + (lr ^ (((k + 2) & 15) << 3))] = v.z;
            As[(k + 3) * 128 + (lr ^ (((k + 3) & 15) << 3))] = v.w;
        }
    }
    __syncthreads();

    for (int bn = 0; bn < 8; bn++) {
        // Output col n = bn*128+lr  ->  W row (gate-last permutation)
        const int ncol = bn * 128 + lr;
        const float* Brow = W + (long)((ncol & 3) * 256 + (ncol >> 2)) * 256;

        unsigned long long acc2[4][8];
#pragma unroll
        for (int i = 0; i < 4; i++)
#pragma unroll
            for (int j = 0; j < 8; j++) acc2[i][j] = 0ull;

        for (int k0 = 0; k0 < 256; k0 += 16) {
            float4 c0 = __ldg((const float4*)(Brow + k0 + kc * 4));
            float4 c1 = __ldg((const float4*)(Brow + k0 + (kc + 2) * 4));
            __syncthreads();
            Bs[(kc*4 + 0) * 128 + lr] = c0.x;
            Bs[(kc*4 + 1) * 128 + lr] = c0.y;
            Bs[(kc*4 + 2) * 128 + lr] = c0.z;
            Bs[(kc*4 + 3) * 128 + lr] = c0.w;
            Bs[((kc+2)*4 + 0) * 128 + lr] = c1.x;
            Bs[((kc+2)*4 + 1) * 128 + lr] = c1.y;
            Bs[((kc+2)*4 + 2) * 128 + lr] = c1.z;
            Bs[((kc+2)*4 + 3) * 128 + lr] = c1.w;
            __syncthreads();
#pragma unroll
            for (int k = 0; k < 16; k++) {
                const int sw = (k & 15) << 3;
                const float* ap = &As[(k0 + k) * 128 + ((ty * 8) ^ sw)];
                ulonglong2 a01 = *(const ulonglong2*)ap;
                ulonglong2 a23 = *(const ulonglong2*)(ap + 4);
                float4 bv0 = *(const float4*)&Bs[k * 128 + tx * 8];
                float4 bv1 = *(const float4*)&Bs[k * 128 + tx * 8 + 4];
                unsigned long long bd[8];
                DUP2(bd[0], bv0.x); DUP2(bd[1], bv0.y);
                DUP2(bd[2], bv0.z); DUP2(bd[3], bv0.w);
                DUP2(bd[4], bv1.x); DUP2(bd[5], bv1.y);
                DUP2(bd[6], bv1.z); DUP2(bd[7], bv1.w);
                unsigned long long ap4[4] = {a01.x, a01.y, a23.x, a23.y};
#pragma unroll
                for (int ip = 0; ip < 4; ip++)
#pragma unroll
                    for (int j = 0; j < 8; j++)
                        FMA2(acc2[ip][j], ap4[ip], bd[j]);
            }
        }

        const int ng = bn * 128 + tx * 8;
        float bias[8];
#pragma unroll
        for (int j = 0; j < 8; j++) {
            int n = ng + j;
            int wrow = (n & 3) * 256 + (n >> 2);
            bias[j] = b1[wrow] + b2[wrow];
        }
        float o[8][8];
#pragma unroll
        for (int ip = 0; ip < 4; ip++)
#pragma unroll
            for (int j = 0; j < 8; j++) {
                float lo, hi;
                UNPK2(lo, hi, acc2[ip][j]);
                o[2*ip][j]   = lo + bias[j];
                o[2*ip+1][j] = hi + bias[j];
            }
#pragma unroll
        for (int i = 0; i < 8; i++) {
            long r = (long)bm * 128 + ty * 8 + i;
            uint4 pk;
            *(__half2*)&pk.x = __floats2half2_rn(o[i][0], o[i][1]);
            *(__half2*)&pk.y = __floats2half2_rn(o[i][2], o[i][3]);
            *(__half2*)&pk.z = __floats2half2_rn(o[i][4], o[i][5]);
            *(__half2*)&pk.w = __floats2half2_rn(o[i][6], o[i][7]);
            *(uint4*)(out + r * 1024 + ng) = pk;
        }
    }
}

// ---------------------------------------------------------------------------
// Kernel 2: persistent BiLSTM.  256 blocks x 128 thr (W in regs, 2/SM).
// fp16 x read (8B), fp16 h_out write, split-phase barrier with the h_out
// store + next-step x prefetch executed in the barrier shadow.
// ---------------------------------------------------------------------------
__global__ __launch_bounds__(128, 2) void lstm_kernel(
    const float* __restrict__ Whhf, const float* __restrict__ Whhb,
    const int* __restrict__ masks)
{
    __shared__ float hsm[8 * 256];
    __shared__ unsigned long long psum[4096];

    const int tid  = threadIdx.x;
    const int lane = tid & 31;
    const int w    = tid >> 5;
    const int bid  = blockIdx.x;
    const int grp  = bid & 15;
    const int dir  = grp >> 3;
    const int b0   = (grp & 7) * 8;
    const int h0   = (bid >> 4) * 16;
    const int hh   = lane & 15;
    const int ks   = w * 2 + (lane >> 4);
    const int bb   = tid >> 4;
    const int hh2  = tid & 15;

    const float* W = dir ? Whhb : Whhf;
    const __half* xp = g_xproj[dir];
    __half* outp = g_hout[dir];

    unsigned exp = 0;
    if (tid == 0) exp = *(volatile unsigned*)&g_ggen[grp * 32];

    unsigned long long wr[4][16];
#pragma unroll
    for (int g = 0; g < 4; g++) {
        const float* wp = W + ((size_t)(g * 256 + h0 + hh)) * 256 + ks * 32;
#pragma unroll
        for (int u = 0; u < 16; u++)
            wr[g][u] = *(const unsigned long long*)(wp + u * 2);
    }

    g_hbuf[dir][0][(b0 + bb) * 256 + h0 + hh2] = 0.f;
    float hreg = 0.f, creg = 0.f;
    group_arrive(grp);
    if (tid == 0) exp += 1;

    float4* hsm4 = (float4*)hsm;
    const ulonglong2* hU2 = (const ulonglong2*)hsm;

    // Prefetch x / mask for step 0.
    const int l0 = dir ? 511 : 0;
    uint2 xraw = __ldg((const uint2*)(
        xp + ((size_t)(l0 * 64 + b0 + bb) * 256 + (h0 + hh2)) * 4));
    int m = __ldg(masks + l0 * 64 + b0 + bb);

    int p = 0;
    for (int step = 0; step < 512; step++) {
        const int l = dir ? (511 - step) : step;

        group_wait(grp, exp);
        if (tid == 0) exp++;

        // Stage h_prev (8 x 256) from L2.
        const float4* hb4 = (const float4*)g_hbuf[dir][p];
#pragma unroll
        for (int i = 0; i < 4; i++) {
            int idx = tid + i * 128;
            hsm4[idx] = __ldcg(hb4 + (b0 + (idx >> 6)) * 64 + (idx & 63));
        }
        __syncthreads();

#pragma unroll
        for (int pass = 0; pass < 2; pass++) {
            unsigned long long acc[4][4];
#pragma unroll
            for (int g = 0; g < 4; g++)
#pragma unroll
                for (int b = 0; b < 4; b++) acc[g][b] = 0ull;
#pragma unroll
            for (int b = 0; b < 4; b++) {
                const ulonglong2* hp = hU2 + (pass * 4 + b) * 64 + ks * 8;
#pragma unroll
                for (int u2 = 0; u2 < 8; u2++) {
                    ulonglong2 hv = hp[u2];
                    FMA2(acc[0][b], wr[0][2*u2], hv.x);
                    FMA2(acc[0][b], wr[0][2*u2+1], hv.y);
                    FMA2(acc[1][b], wr[1][2*u2], hv.x);
                    FMA2(acc[1][b], wr[1][2*u2+1], hv.y);
                    FMA2(acc[2][b], wr[2][2*u2], hv.x);
                    FMA2(acc[2][b], wr[2][2*u2+1], hv.y);
                    FMA2(acc[3][b], wr[3][2*u2], hv.x);
                    FMA2(acc[3][b], wr[3][2*u2+1], hv.y);
                }
            }
#pragma unroll
            for (int g = 0; g < 4; g++)
#pragma unroll
                for (int b = 0; b < 4; b++)
                    psum[((ks * 4 + g) * 8 + pass * 4 + b) * 16 + hh] = acc[g][b];
        }
        __syncthreads();

        unsigned long long s0 = 0ull, s1 = 0ull, s2 = 0ull, s3 = 0ull;
#pragma unroll
        for (int k2 = 0; k2 < 8; k2++) {
            ADD2(s0, psum[((k2 * 4 + 0) * 8 + bb) * 16 + hh2]);
            ADD2(s1, psum[((k2 * 4 + 1) * 8 + bb) * 16 + hh2]);
            ADD2(s2, psum[((k2 * 4 + 2) * 8 + bb) * 16 + hh2]);
            ADD2(s3, psum[((k2 * 4 + 3) * 8 + bb) * 16 + hh2]);
        }
        float lo, hi, f0, f1, f2, f3;
        UNPK2(lo, hi, s0); f0 = lo + hi;
        UNPK2(lo, hi, s1); f1 = lo + hi;
        UNPK2(lo, hi, s2); f2 = lo + hi;
        UNPK2(lo, hi, s3); f3 = lo + hi;

        float2 x01 = __half22float2(*(__half2*)&xraw.x);
        float2 x23 = __half22float2(*(__half2*)&xraw.y);

        float gi = 1.f / (1.f + __expf(-(x01.x + f0)));
        float gf = 1.f / (1.f + __expf(-(x01.y + f1)));
        float gg = tanhf(x23.x + f2);
        float go = 1.f / (1.f + __expf(-(x23.y + f3)));
        float cn = gf * creg + gi * gg;
        float hn = go * tanhf(cn);
        float outv;
        if (m) { creg = cn; hreg = hn; outv = hn; } else { outv = 0.f; }

        g_hbuf[dir][p ^ 1][(b0 + bb) * 256 + h0 + hh2] = hreg;
        group_arrive(grp);

        // Barrier shadow: h_out store + next-step prefetch.
        outp[((size_t)(l * 64 + b0 + bb)) * 256 + h0 + hh2] = __float2half_rn(outv);
        const int sn = (step < 511) ? step + 1 : 511;
        const int ln = dir ? (511 - sn) : sn;
        xraw = __ldg((const uint2*)(
            xp + ((size_t)(ln * 64 + b0 + bb) * 256 + (h0 + hh2)) * 4));
        m = __ldg(masks + ln * 64 + b0 + bb);

        p ^= 1;
    }
}

// ---------------------------------------------------------------------------
// Kernel 3a: transpose W_out (T,512) -> g_WoutT (512,T).
// ---------------------------------------------------------------------------
__global__ void wtrans_kernel(const float* __restrict__ Wout) {
    int idx = blockIdx.x * 256 + threadIdx.x;
    if (idx < 512 * NT) {
        int k = idx >> 5, t = idx & 31;
        g_WoutT[idx] = Wout[t * 512 + k];
    }
}

// ---------------------------------------------------------------------------
// Kernel 3b: emissions = [h_f | h_b] @ W_out^T + b_out.  fp16 h staging.
// ---------------------------------------------------------------------------
#define WT_PAD 514
#define EMIS_SMEM_BYTES ((32 * WT_PAD + 8 * 512) * 4)
__global__ __launch_bounds__(256) void emis_kernel(const float* __restrict__ bout)
{
    extern __shared__ float sm[];
    float* wsmT = sm;                   // [32 t][514]
    float* hsm  = sm + 32 * WT_PAD;     // [8 r][512]
    const int tid = threadIdx.x;
    const int r = tid >> 5, t = tid & 31;
    const float bb = bout[t];

    for (int i = 0; i < 64; i++) {
        int idx = tid + i * 256;
        int k = idx >> 5, tt = idx & 31;
        wsmT[tt * WT_PAD + k] = g_WoutT[idx];
    }

    const uint4* h0p = (const uint4*)g_hout[0];   // row stride: 32 uint4
    const uint4* h1p = (const uint4*)g_hout[1];

    for (int it = 0; it < 4; it++) {
        const int bm = blockIdx.x * 4 + it;       // 0..4095
        __syncthreads();
#pragma unroll
        for (int i = 0; i < 2; i++) {
            int s = tid + i * 256;                // 0..511 (8-half groups)
            int rr = s >> 6, c8 = s & 63;
            size_t row = (size_t)bm * 8 + rr;
            uint4 v = (c8 < 32) ? __ldg(h0p + row * 32 + c8)
                                : __ldg(h1p + row * 32 + (c8 - 32));
            int cb = (c8 < 32) ? c8 * 8 : 256 + (c8 - 32) * 8;
            float* dst = hsm + rr * 512 + cb;
            float2 f0 = __half22float2(*(__half2*)&v.x);
            float2 f1 = __half22float2(*(__half2*)&v.y);
            float2 f2 = __half22float2(*(__half2*)&v.z);
            float2 f3 = __half22float2(*(__half2*)&v.w);
            *(float4*)dst       = make_float4(f0.x, f0.y, f1.x, f1.y);
            *(float4*)(dst + 4) = make_float4(f2.x, f2.y, f3.x, f3.y);
        }
        __syncthreads();

        const float* hr = hsm + r * 512;
        const float* wr = wsmT + t * WT_PAD;
        unsigned long long a0 = 0ull, a1 = 0ull, a2 = 0ull, a3 = 0ull;
#pragma unroll 4
        for (int k = 0; k < 512; k += 16) {
            ulonglong2 hA = *(const ulonglong2*)(hr + k);
            ulonglong2 hB = *(const ulonglong2*)(hr + k + 4);
            ulonglong2 hC = *(const ulonglong2*)(hr + k + 8);
            ulonglong2 hD = *(const ulonglong2*)(hr + k + 12);
            FMA2(a0, hA.x, *(const unsigned long long*)(wr + k));
            FMA2(a0, hA.y, *(const unsigned long long*)(wr + k + 2));
            FMA2(a1, hB.x, *(const unsigned long long*)(wr + k + 4));
            FMA2(a1, hB.y, *(const unsigned long long*)(wr + k + 6));
            FMA2(a2, hC.x, *(const unsigned long long*)(wr + k + 8));
            FMA2(a2, hC.y, *(const unsigned long long*)(wr + k + 10));
            FMA2(a3, hD.x, *(const unsigned long long*)(wr + k + 12));
            FMA2(a3, hD.y, *(const unsigned long long*)(wr + k + 14));
        }
        ADD2(a0, a1); ADD2(a2, a3); ADD2(a0, a2);
        float lo, hi;
        UNPK2(lo, hi, a0);
        g_em[((size_t)bm * 8 + r) * 32 + t] = lo + hi + bb;
    }
}

// ---------------------------------------------------------------------------
// Kernel 4: CRF.  128 threads per batch (4-warp split LSE merge).
// ---------------------------------------------------------------------------
__global__ __launch_bounds__(128) void crf_kernel(
    const int* __restrict__ tags, const int* __restrict__ masks,
    const float* __restrict__ start_trans, const float* __restrict__ end_trans,
    const float* __restrict__ trans)
{
    __shared__ float tsm[NT * NT];
    __shared__ float ssm[NT];
    __shared__ float pm[4][NT];
    __shared__ float ps[4][NT];
    __shared__ float redf[8];
    __shared__ int   redi[8];

    const int b = blockIdx.x;
    const int tid = threadIdx.x;
    const int w = tid >> 5;
    const int j = tid & 31;

    for (int i = tid; i < NT * NT; i += 128) tsm[i] = trans[i];
    if (w == 0) ssm[j] = start_trans[j] + g_em[(size_t)b * 32 + j];
    __syncthreads();

    for (int l = 1; l < 512; l++) {
        float v[8];
        float mx = -3.4e38f;
#pragma unroll
        for (int ii = 0; ii < 8; ii++) {
            int i = w * 8 + ii;
            v[ii] = ssm[i] + tsm[i * 32 + j];
            mx = fmaxf(mx, v[ii]);
        }
        float s = 0.f;
#pragma unroll
        for (int ii = 0; ii < 8; ii++) s += __expf(v[ii] - mx);
        pm[w][j] = mx;
        ps[w][j] = s;
        __syncthreads();
        if (w == 0) {
            float m0 = pm[0][j], m1 = pm[1][j], m2 = pm[2][j], m3 = pm[3][j];
            float M = fmaxf(fmaxf(m0, m1), fmaxf(m2, m3));
            float S = ps[0][j] * __expf(m0 - M) + ps[1][j] * __expf(m1 - M)
                    + ps[2][j] * __expf(m2 - M) + ps[3][j] * __expf(m3 - M);
            float nxt = M + __logf(S) + g_em[((size_t)(l * 64 + b)) * 32 + j];
            if (masks[l * 64 + b]) ssm[j] = nxt;
        }
        __syncthreads();
    }

    float part = 0.f;
    int lenp = 0;
    for (int l = tid; l < 512; l += 128) {
        int m = masks[l * 64 + b];
        lenp += m;
        int tg = tags[l * 64 + b];
        float e = g_em[((size_t)(l * 64 + b)) * 32 + tg];
        if (l == 0) {
            part += start_trans[tg] + e;
        } else {
            int tp = tags[(l - 1) * 64 + b];
            part += (e + tsm[tp * 32 + tg]) * (float)m;
        }
    }
#pragma unroll
    for (int off = 16; off > 0; off >>= 1) {
        part += __shfl_xor_sync(0xffffffffu, part, off);
        lenp += __shfl_xor_sync(0xffffffffu, lenp, off);
    }
    if (j == 0) { redf[w] = part; redi[w] = lenp; }
    __syncthreads();

    if (w == 0) {
        float num_p = redf[0] + redf[1] + redf[2] + redf[3];
        int   length = redi[0] + redi[1] + redi[2] + redi[3];

        float tv = ssm[j] + end_trans[j];
        float mx = tv;
#pragma unroll
        for (int off = 16; off > 0; off >>= 1)
            mx = fmaxf(mx, __shfl_xor_sync(0xffffffffu, mx, off));
        float ex = __expf(tv - mx);
#pragma unroll
        for (int off = 16; off > 0; off >>= 1)
            ex += __shfl_xor_sync(0xffffffffu, ex, off);
        float logz = mx + __logf(ex);

        if (j == 0) {
            int last = tags[(length - 1) * 64 + b];
            g_llh[b] = (num_p + end_trans[last]) - logz;
        }
    }
}

// ---------------------------------------------------------------------------
// Kernel 5: out = -mean(llh)
// ---------------------------------------------------------------------------
__global__ void final_kernel(float* __restrict__ out) {
    if (threadIdx.x == 0) {
        float s = 0.f;
        for (int i = 0; i < NB; i++) s += g_llh[i];
        out[0] = -s / (float)NB;
    }
}

// ---------------------------------------------------------------------------
extern "C" void kernel_launch(void* const* d_in, const int* in_sizes, int n_in,
                              void* d_out, int out_size) {
    const int*   seqs        = (const int*)d_in[0];
    const int*   tags        = (const int*)d_in[1];
    const int*   masks       = (const int*)d_in[2];
    const float* embed       = (const float*)d_in[3];
    const float* W_ih_f      = (const float*)d_in[4];
    const float* W_hh_f      = (const float*)d_in[5];
    const float* b_ih_f      = (const float*)d_in[6];
    const float* b_hh_f      = (const float*)d_in[7];
    const float* W_ih_b      = (const float*)d_in[8];
    const float* W_hh_b      = (const float*)d_in[9];
    const float* b_ih_b      = (const float*)d_in[10];
    const float* b_hh_b      = (const float*)d_in[11];
    const float* W_out       = (const float*)d_in[12];
    const float* b_out       = (const float*)d_in[13];
    const float* start_trans = (const float*)d_in[14];
    const float* end_trans   = (const float*)d_in[15];
    const float* trans       = (const float*)d_in[16];

    cudaFuncSetAttribute(xproj_kernel, cudaFuncAttributeMaxDynamicSharedMemorySize,
                         XP_SMEM_BYTES);
    cudaFuncSetAttribute(emis_kernel, cudaFuncAttributeMaxDynamicSharedMemorySize,
                         EMIS_SMEM_BYTES);

    dim3 xg(256, 2);
    xproj_kernel<<<xg, 256, XP_SMEM_BYTES>>>(embed, seqs, W_ih_f, W_ih_b,
                                             b_ih_f, b_hh_f, b_ih_b, b_hh_b);
    wtrans_kernel<<<64, 256>>>(W_out);
    lstm_kernel<<<256, 128>>>(W_hh_f, W_hh_b, masks);
    emis_kernel<<<1024, 256, EMIS_SMEM_BYTES>>>(b_out);
    crf_kernel<<<64, 128>>>(tags, masks, start_trans, end_trans, trans);
    final_kernel<<<1, 32>>>((float*)d_out);
}

// round 15
// speedup vs baseline: 1.3072x; 1.1314x over previous
#include <cuda_runtime.h>
#include <cuda_bf16.h>
#include <cuda_fp16.h>

// Problem dims
#define SL 512   // sequence length L
#define NB 64    // batch
#define NE 256   // embed dim E
#define NH 256   // hidden H
#define NG 1024  // 4*H
#define NT 32    // tags T

// ---------------------------------------------------------------------------
// Packed f32x2 helpers
// ---------------------------------------------------------------------------
#define FMA2(acc, a, b) \
    asm("fma.rn.f32x2 %0, %1, %2, %0;" : "+l"(acc) : "l"(a), "l"(b))
#define ADD2(acc, v) \
    asm("add.rn.f32x2 %0, %0, %1;" : "+l"(acc) : "l"(v))
#define DUP2(d, s) do { unsigned _u = __float_as_uint(s); \
    asm("mov.b64 %0, {%1, %1};" : "=l"(d) : "r"(_u)); } while (0)
#define UNPK2(lo, hi, v) do { unsigned _a, _b; \
    asm("mov.b64 {%0, %1}, %2;" : "=r"(_a), "=r"(_b) : "l"(v)); \
    lo = __uint_as_float(_a); hi = __uint_as_float(_b); } while (0)
#define TANHA(d, x) asm("tanh.approx.f32 %0, %1;" : "=f"(d) : "f"(x))
// __half2 (as uint) -> packed f32x2 in a u64
#define H2F2(d, h2u) do { __half2 _h = *(__half2*)&(h2u); \
    float2 _f = __half22float2(_h); \
    asm("mov.b64 %0, {%1, %2};" : "=l"(d) : "f"(_f.x), "f"(_f.y)); } while (0)

// ---------------------------------------------------------------------------
// Device-global scratch.  x_proj / h_out fp16; x_proj GATE-LAST [l][b][h][g].
// ---------------------------------------------------------------------------
__device__ __half    g_xproj[2][(size_t)SL * NB * NG];
__device__ __half    g_hout [2][(size_t)SL * NB * NH];
__device__ float     g_em   [(size_t)SL * NB * NT];
__device__ float     g_hbuf [2][2][NB * NH];
__device__ float     g_WoutT[512 * NT];
__device__ float     g_llh  [NB];
// Peer-flag barrier: one monotonic flag per block, 16 blocks per group.
__device__ unsigned  g_flag[16][32];   // [group][sub] padded to 128B rows

// ---------------------------------------------------------------------------
// Kernel 1: x_proj (A-stationary, FFMA2, fp16 gate-last output). grid=(256,2)
// ---------------------------------------------------------------------------
#define XP_SMEM_BYTES ((256 * 128 + 16 * 128) * 4)   // 139264
__global__ __launch_bounds__(256) void xproj_kernel(
    const float* __restrict__ embed, const int* __restrict__ seqs,
    const float* __restrict__ Wf, const float* __restrict__ Wb,
    const float* __restrict__ bihf, const float* __restrict__ bhhf,
    const float* __restrict__ bihb, const float* __restrict__ bhhb)
{
    extern __shared__ float xsm[];
    float* As = xsm;             // [256 k][128 m], phys col = m ^ ((k&15)<<3)
    float* Bs = xsm + 32768;     // [16 k][128 n]

    const int dir = blockIdx.y;
    const float* W  = dir ? Wb   : Wf;
    const float* b1 = dir ? bihb : bihf;
    const float* b2 = dir ? bhhb : bhhf;
    __half* out = g_xproj[dir];

    const int tid = threadIdx.x;
    const int bm = blockIdx.x;
    const int tx = tid & 15;
    const int ty = tid >> 4;
    const int lr = tid & 127;
    const int kc = tid >> 7;

    {
        const long arow = (long)seqs[bm * 128 + lr] * 256 + kc * 128;
        const float* src = embed + arow;
#pragma unroll
        for (int kk = 0; kk < 128; kk += 4) {
            float4 v = __ldg((const float4*)(src + kk));
            int k = kc * 128 + kk;
            As[(k + 0) * 128 + (lr ^ (((k + 0) & 15) << 3))] = v.x;
            As[(k + 1) * 128 + (lr ^ (((k + 1) & 15) << 3))] = v.y;
            As[(k + 2) * 128 + (lr ^ (((k + 2) & 15) << 3))] = v.z;
            As[(k + 3) * 128 + (lr ^ (((k + 3) & 15) << 3))] = v.w;
        }
    }
    __syncthreads();

    for (int bn = 0; bn < 8; bn++) {
        const int ncol = bn * 128 + lr;
        const float* Brow = W + (long)((ncol & 3) * 256 + (ncol >> 2)) * 256;

        unsigned long long acc2[4][8];
#pragma unroll
        for (int i = 0; i < 4; i++)
#pragma unroll
            for (int j = 0; j < 8; j++) acc2[i][j] = 0ull;

        for (int k0 = 0; k0 < 256; k0 += 16) {
            float4 c0 = __ldg((const float4*)(Brow + k0 + kc * 4));
            float4 c1 = __ldg((const float4*)(Brow + k0 + (kc + 2) * 4));
            __syncthreads();
            Bs[(kc*4 + 0) * 128 + lr] = c0.x;
            Bs[(kc*4 + 1) * 128 + lr] = c0.y;
            Bs[(kc*4 + 2) * 128 + lr] = c0.z;
            Bs[(kc*4 + 3) * 128 + lr] = c0.w;
            Bs[((kc+2)*4 + 0) * 128 + lr] = c1.x;
            Bs[((kc+2)*4 + 1) * 128 + lr] = c1.y;
            Bs[((kc+2)*4 + 2) * 128 + lr] = c1.z;
            Bs[((kc+2)*4 + 3) * 128 + lr] = c1.w;
            __syncthreads();
#pragma unroll
            for (int k = 0; k < 16; k++) {
                const int sw = (k & 15) << 3;
                const float* ap = &As[(k0 + k) * 128 + ((ty * 8) ^ sw)];
                ulonglong2 a01 = *(const ulonglong2*)ap;
                ulonglong2 a23 = *(const ulonglong2*)(ap + 4);
                float4 bv0 = *(const float4*)&Bs[k * 128 + tx * 8];
                float4 bv1 = *(const float4*)&Bs[k * 128 + tx * 8 + 4];
                unsigned long long bd[8];
                DUP2(bd[0], bv0.x); DUP2(bd[1], bv0.y);
                DUP2(bd[2], bv0.z); DUP2(bd[3], bv0.w);
                DUP2(bd[4], bv1.x); DUP2(bd[5], bv1.y);
                DUP2(bd[6], bv1.z); DUP2(bd[7], bv1.w);
                unsigned long long ap4[4] = {a01.x, a01.y, a23.x, a23.y};
#pragma unroll
                for (int ip = 0; ip < 4; ip++)
#pragma unroll
                    for (int j = 0; j < 8; j++)
                        FMA2(acc2[ip][j], ap4[ip], bd[j]);
            }
        }

        const int ng = bn * 128 + tx * 8;
        float bias[8];
#pragma unroll
        for (int j = 0; j < 8; j++) {
            int n = ng + j;
            int wrow = (n & 3) * 256 + (n >> 2);
            bias[j] = b1[wrow] + b2[wrow];
        }
        float o[8][8];
#pragma unroll
        for (int ip = 0; ip < 4; ip++)
#pragma unroll
            for (int j = 0; j < 8; j++) {
                float lo, hi;
                UNPK2(lo, hi, acc2[ip][j]);
                o[2*ip][j]   = lo + bias[j];
                o[2*ip+1][j] = hi + bias[j];
            }
#pragma unroll
        for (int i = 0; i < 8; i++) {
            long r = (long)bm * 128 + ty * 8 + i;
            uint4 pk;
            *(__half2*)&pk.x = __floats2half2_rn(o[i][0], o[i][1]);
            *(__half2*)&pk.y = __floats2half2_rn(o[i][2], o[i][3]);
            *(__half2*)&pk.z = __floats2half2_rn(o[i][4], o[i][5]);
            *(__half2*)&pk.w = __floats2half2_rn(o[i][6], o[i][7]);
            *(uint4*)(out + r * 1024 + ng) = pk;
        }
    }
}

// ---------------------------------------------------------------------------
// Kernel 2: persistent BiLSTM.  Peer-flag barrier (parallel poll, no atomic
// chain), tanh.approx gates, W in regs, split-phase with barrier-shadow
// h_out store + x prefetch.  256 blocks x 128 thr, 2/SM.
// ---------------------------------------------------------------------------
__global__ __launch_bounds__(128, 2) void lstm_kernel(
    const float* __restrict__ Whhf, const float* __restrict__ Whhb,
    const int* __restrict__ masks)
{
    __shared__ float hsm[8 * 256];
    __shared__ unsigned long long psum[4096];

    const int tid  = threadIdx.x;
    const int lane = tid & 31;
    const int w    = tid >> 5;
    const int bid  = blockIdx.x;
    const int grp  = bid & 15;           // barrier group (dir x batch-octet)
    const int sub  = bid >> 4;           // 0..15 within group
    const int dir  = grp >> 3;
    const int b0   = (grp & 7) * 8;
    const int h0   = sub * 16;
    const int hh   = lane & 15;
    const int ks   = w * 2 + (lane >> 4);
    const int bb   = tid >> 4;
    const int hh2  = tid & 15;

    const float* W = dir ? Whhb : Whhf;
    const __half* xp = g_xproj[dir];
    __half* outp = g_hout[dir];

    // Monotonic flag base (own slot; all slots in a group are equal at entry).
    const unsigned base = *(volatile unsigned*)&g_flag[grp][sub];

    unsigned long long wr[4][16];
#pragma unroll
    for (int g = 0; g < 4; g++) {
        const float* wp = W + ((size_t)(g * 256 + h0 + hh)) * 256 + ks * 32;
#pragma unroll
        for (int u = 0; u < 16; u++)
            wr[g][u] = *(const unsigned long long*)(wp + u * 2);
    }

    // Publish initial h = 0, then arrive (#1).
    g_hbuf[dir][0][(b0 + bb) * 256 + h0 + hh2] = 0.f;
    float hreg = 0.f, creg = 0.f;
    __threadfence();
    __syncthreads();
    if (tid == 0) *(volatile unsigned*)&g_flag[grp][sub] = base + 1u;

    float4* hsm4 = (float4*)hsm;
    const ulonglong2* hU2 = (const ulonglong2*)hsm;

    // Prefetch x / mask for step 0.
    const int l0 = dir ? 511 : 0;
    uint2 xraw = __ldg((const uint2*)(
        xp + ((size_t)(l0 * 64 + b0 + bb) * 256 + (h0 + hh2)) * 4));
    int m = __ldg(masks + l0 * 64 + b0 + bb);

    int p = 0;
    for (int step = 0; step < 512; step++) {
        const int l = dir ? (511 - step) : step;

        // Wait: 16 lanes poll the 16 peer flags in parallel.
        {
            const unsigned target = base + 1u + (unsigned)step;
            if (tid < 16) {
                volatile unsigned* f = &g_flag[grp][tid];
                while ((int)(*f - target) < 0) { }
            }
            __syncthreads();
        }

        // Stage h_prev (8 x 256) from L2.
        const float4* hb4 = (const float4*)g_hbuf[dir][p];
#pragma unroll
        for (int i = 0; i < 4; i++) {
            int idx = tid + i * 128;
            hsm4[idx] = __ldcg(hb4 + (b0 + (idx >> 6)) * 64 + (idx & 63));
        }
        __syncthreads();

#pragma unroll
        for (int pass = 0; pass < 2; pass++) {
            unsigned long long acc[4][4];
#pragma unroll
            for (int g = 0; g < 4; g++)
#pragma unroll
                for (int b = 0; b < 4; b++) acc[g][b] = 0ull;
#pragma unroll
            for (int b = 0; b < 4; b++) {
                const ulonglong2* hp = hU2 + (pass * 4 + b) * 64 + ks * 8;
#pragma unroll
                for (int u2 = 0; u2 < 8; u2++) {
                    ulonglong2 hv = hp[u2];
                    FMA2(acc[0][b], wr[0][2*u2], hv.x);
                    FMA2(acc[0][b], wr[0][2*u2+1], hv.y);
                    FMA2(acc[1][b], wr[1][2*u2], hv.x);
                    FMA2(acc[1][b], wr[1][2*u2+1], hv.y);
                    FMA2(acc[2][b], wr[2][2*u2], hv.x);
                    FMA2(acc[2][b], wr[2][2*u2+1], hv.y);
                    FMA2(acc[3][b], wr[3][2*u2], hv.x);
                    FMA2(acc[3][b], wr[3][2*u2+1], hv.y);
                }
            }
#pragma unroll
            for (int g = 0; g < 4; g++)
#pragma unroll
                for (int b = 0; b < 4; b++)
                    psum[((ks * 4 + g) * 8 + pass * 4 + b) * 16 + hh] = acc[g][b];
        }
        __syncthreads();

        unsigned long long s0 = 0ull, s1 = 0ull, s2 = 0ull, s3 = 0ull;
#pragma unroll
        for (int k2 = 0; k2 < 8; k2++) {
            ADD2(s0, psum[((k2 * 4 + 0) * 8 + bb) * 16 + hh2]);
            ADD2(s1, psum[((k2 * 4 + 1) * 8 + bb) * 16 + hh2]);
            ADD2(s2, psum[((k2 * 4 + 2) * 8 + bb) * 16 + hh2]);
            ADD2(s3, psum[((k2 * 4 + 3) * 8 + bb) * 16 + hh2]);
        }
        float lo, hi, f0, f1, f2, f3;
        UNPK2(lo, hi, s0); f0 = lo + hi;
        UNPK2(lo, hi, s1); f1 = lo + hi;
        UNPK2(lo, hi, s2); f2 = lo + hi;
        UNPK2(lo, hi, s3); f3 = lo + hi;

        float2 x01 = __half22float2(*(__half2*)&xraw.x);
        float2 x23 = __half22float2(*(__half2*)&xraw.y);

        // Gates via single-instruction tanh.approx.
        float ti, tf, tg, to;
        TANHA(ti, 0.5f * (x01.x + f0));
        TANHA(tf, 0.5f * (x01.y + f1));
        TANHA(tg, x23.x + f2);
        TANHA(to, 0.5f * (x23.y + f3));
        float gi = fmaf(0.5f, ti, 0.5f);
        float gf = fmaf(0.5f, tf, 0.5f);
        float go = fmaf(0.5f, to, 0.5f);
        float cn = gf * creg + gi * tg;
        float tc; TANHA(tc, cn);
        float hn = go * tc;
        float outv;
        if (m) { creg = cn; hreg = hn; outv = hn; } else { outv = 0.f; }

        // Publish h, fence, arrive.
        g_hbuf[dir][p ^ 1][(b0 + bb) * 256 + h0 + hh2] = hreg;
        __threadfence();
        __syncthreads();
        if (tid == 0)
            *(volatile unsigned*)&g_flag[grp][sub] = base + 2u + (unsigned)step;

        // Barrier shadow: h_out store + next-step prefetch.
        outp[((size_t)(l * 64 + b0 + bb)) * 256 + h0 + hh2] = __float2half_rn(outv);
        const int sn = (step < 511) ? step + 1 : 511;
        const int ln = dir ? (511 - sn) : sn;
        xraw = __ldg((const uint2*)(
            xp + ((size_t)(ln * 64 + b0 + bb) * 256 + (h0 + hh2)) * 4));
        m = __ldg(masks + ln * 64 + b0 + bb);

        p ^= 1;
    }
}

// ---------------------------------------------------------------------------
// Kernel 3a: transpose W_out (T,512) -> g_WoutT (512,T).
// ---------------------------------------------------------------------------
__global__ void wtrans_kernel(const float* __restrict__ Wout) {
    int idx = blockIdx.x * 256 + threadIdx.x;
    if (idx < 512 * NT) {
        int k = idx >> 5, t = idx & 31;
        g_WoutT[idx] = Wout[t * 512 + k];
    }
}

// ---------------------------------------------------------------------------
// Kernel 3b: emissions.  W in smem as fp16 (row pad 520 halves = 1040B,
// 16B-aligned rows -> aligned uint2 loads) -> ~49KB smem -> 4 blocks/SM.
// ---------------------------------------------------------------------------
#define WPADH 520
#define EMIS_SMEM_BYTES (32 * WPADH * 2 + 8 * 512 * 4)   // 49664
__global__ __launch_bounds__(256) void emis_kernel(const float* __restrict__ bout)
{
    extern __shared__ char esm[];
    __half* wsmT = (__half*)esm;                    // [32 t][520 k] fp16
    float*  hsm  = (float*)(esm + 32 * WPADH * 2);  // [8 r][512]
    const int tid = threadIdx.x;
    const int r = tid >> 5, t = tid & 31;
    const float bb = bout[t];

    for (int i = 0; i < 64; i++) {
        int idx = tid + i * 256;                    // 0..16383 (k*32+t)
        int k = idx >> 5, tt = idx & 31;
        wsmT[tt * WPADH + k] = __float2half_rn(g_WoutT[idx]);
    }

    const uint4* h0p = (const uint4*)g_hout[0];
    const uint4* h1p = (const uint4*)g_hout[1];

    for (int it = 0; it < 4; it++) {
        const int bm = blockIdx.x * 4 + it;
        __syncthreads();
#pragma unroll
        for (int i = 0; i < 2; i++) {
            int s = tid + i * 256;
            int rr = s >> 6, c8 = s & 63;
            size_t row = (size_t)bm * 8 + rr;
            uint4 v = (c8 < 32) ? __ldg(h0p + row * 32 + c8)
                                : __ldg(h1p + row * 32 + (c8 - 32));
            int cb = (c8 < 32) ? c8 * 8 : 256 + (c8 - 32) * 8;
            float* dst = hsm + rr * 512 + cb;
            float2 f0 = __half22float2(*(__half2*)&v.x);
            float2 f1 = __half22float2(*(__half2*)&v.y);
            float2 f2 = __half22float2(*(__half2*)&v.z);
            float2 f3 = __half22float2(*(__half2*)&v.w);
            *(float4*)dst       = make_float4(f0.x, f0.y, f1.x, f1.y);
            *(float4*)(dst + 4) = make_float4(f2.x, f2.y, f3.x, f3.y);
        }
        __syncthreads();

        const float*  hr = hsm + r * 512;
        const __half* wrh = wsmT + t * WPADH;
        unsigned long long a0 = 0ull, a1 = 0ull, a2 = 0ull, a3 = 0ull;
#pragma unroll 4
        for (int k = 0; k < 512; k += 16) {
            ulonglong2 hA = *(const ulonglong2*)(hr + k);
            ulonglong2 hB = *(const ulonglong2*)(hr + k + 4);
            ulonglong2 hC = *(const ulonglong2*)(hr + k + 8);
            ulonglong2 hD = *(const ulonglong2*)(hr + k + 12);
            uint2 wA = *(const uint2*)(wrh + k);
            uint2 wB = *(const uint2*)(wrh + k + 4);
            uint2 wC = *(const uint2*)(wrh + k + 8);
            uint2 wD = *(const uint2*)(wrh + k + 12);
            unsigned long long w0, w1, w2, w3, w4, w5, w6, w7;
            H2F2(w0, wA.x); H2F2(w1, wA.y);
            H2F2(w2, wB.x); H2F2(w3, wB.y);
            H2F2(w4, wC.x); H2F2(w5, wC.y);
            H2F2(w6, wD.x); H2F2(w7, wD.y);
            FMA2(a0, hA.x, w0); FMA2(a0, hA.y, w1);
            FMA2(a1, hB.x, w2); FMA2(a1, hB.y, w3);
            FMA2(a2, hC.x, w4); FMA2(a2, hC.y, w5);
            FMA2(a3, hD.x, w6); FMA2(a3, hD.y, w7);
        }
        ADD2(a0, a1); ADD2(a2, a3); ADD2(a0, a2);
        float lo, hi;
        UNPK2(lo, hi, a0);
        g_em[((size_t)bm * 8 + r) * 32 + t] = lo + hi + bb;
    }
}

// ---------------------------------------------------------------------------
// Kernel 4: CRF.  128 threads per batch (4-warp split LSE merge).
// ---------------------------------------------------------------------------
__global__ __launch_bounds__(128) void crf_kernel(
    const int* __restrict__ tags, const int* __restrict__ masks,
    const float* __restrict__ start_trans, const float* __restrict__ end_trans,
    const float* __restrict__ trans)
{
    __shared__ float tsm[NT * NT];
    __shared__ float ssm[NT];
    __shared__ float pm[4][NT];
    __shared__ float ps[4][NT];
    __shared__ float redf[8];
    __shared__ int   redi[8];

    const int b = blockIdx.x;
    const int tid = threadIdx.x;
    const int w = tid >> 5;
    const int j = tid & 31;

    for (int i = tid; i < NT * NT; i += 128) tsm[i] = trans[i];
    if (w == 0) ssm[j] = start_trans[j] + g_em[(size_t)b * 32 + j];
    __syncthreads();

    for (int l = 1; l < 512; l++) {
        float v[8];
        float mx = -3.4e38f;
#pragma unroll
        for (int ii = 0; ii < 8; ii++) {
            int i = w * 8 + ii;
            v[ii] = ssm[i] + tsm[i * 32 + j];
            mx = fmaxf(mx, v[ii]);
        }
        float s = 0.f;
#pragma unroll
        for (int ii = 0; ii < 8; ii++) s += __expf(v[ii] - mx);
        pm[w][j] = mx;
        ps[w][j] = s;
        __syncthreads();
        if (w == 0) {
            float m0 = pm[0][j], m1 = pm[1][j], m2 = pm[2][j], m3 = pm[3][j];
            float M = fmaxf(fmaxf(m0, m1), fmaxf(m2, m3));
            float S = ps[0][j] * __expf(m0 - M) + ps[1][j] * __expf(m1 - M)
                    + ps[2][j] * __expf(m2 - M) + ps[3][j] * __expf(m3 - M);
            float nxt = M + __logf(S) + g_em[((size_t)(l * 64 + b)) * 32 + j];
            if (masks[l * 64 + b]) ssm[j] = nxt;
        }
        __syncthreads();
    }

    float part = 0.f;
    int lenp = 0;
    for (int l = tid; l < 512; l += 128) {
        int m = masks[l * 64 + b];
        lenp += m;
        int tg = tags[l * 64 + b];
        float e = g_em[((size_t)(l * 64 + b)) * 32 + tg];
        if (l == 0) {
            part += start_trans[tg] + e;
        } else {
            int tp = tags[(l - 1) * 64 + b];
            part += (e + tsm[tp * 32 + tg]) * (float)m;
        }
    }
#pragma unroll
    for (int off = 16; off > 0; off >>= 1) {
        part += __shfl_xor_sync(0xffffffffu, part, off);
        lenp += __shfl_xor_sync(0xffffffffu, lenp, off);
    }
    if (j == 0) { redf[w] = part; redi[w] = lenp; }
    __syncthreads();

    if (w == 0) {
        float num_p = redf[0] + redf[1] + redf[2] + redf[3];
        int   length = redi[0] + redi[1] + redi[2] + redi[3];

        float tv = ssm[j] + end_trans[j];
        float mx = tv;
#pragma unroll
        for (int off = 16; off > 0; off >>= 1)
            mx = fmaxf(mx, __shfl_xor_sync(0xffffffffu, mx, off));
        float ex = __expf(tv - mx);
#pragma unroll
        for (int off = 16; off > 0; off >>= 1)
            ex += __shfl_xor_sync(0xffffffffu, ex, off);
        float logz = mx + __logf(ex);

        if (j == 0) {
            int last = tags[(length - 1) * 64 + b];
            g_llh[b] = (num_p + end_trans[last]) - logz;
        }
    }
}

// ---------------------------------------------------------------------------
// Kernel 5: out = -mean(llh)
// ---------------------------------------------------------------------------
__global__ void final_kernel(float* __restrict__ out) {
    if (threadIdx.x == 0) {
        float s = 0.f;
        for (int i = 0; i < NB; i++) s += g_llh[i];
        out[0] = -s / (float)NB;
    }
}

// ---------------------------------------------------------------------------
extern "C" void kernel_launch(void* const* d_in, const int* in_sizes, int n_in,
                              void* d_out, int out_size) {
    const int*   seqs        = (const int*)d_in[0];
    const int*   tags        = (const int*)d_in[1];
    const int*   masks       = (const int*)d_in[2];
    const float* embed       = (const float*)d_in[3];
    const float* W_ih_f      = (const float*)d_in[4];
    const float* W_hh_f      = (const float*)d_in[5];
    const float* b_ih_f      = (const float*)d_in[6];
    const float* b_hh_f      = (const float*)d_in[7];
    const float* W_ih_b      = (const float*)d_in[8];
    const float* W_hh_b      = (const float*)d_in[9];
    const float* b_ih_b      = (const float*)d_in[10];
    const float* b_hh_b      = (const float*)d_in[11];
    const float* W_out       = (const float*)d_in[12];
    const float* b_out       = (const float*)d_in[13];
    const float* start_trans = (const float*)d_in[14];
    const float* end_trans   = (const float*)d_in[15];
    const float* trans       = (const float*)d_in[16];

    cudaFuncSetAttribute(xproj_kernel, cudaFuncAttributeMaxDynamicSharedMemorySize,
                         XP_SMEM_BYTES);
    cudaFuncSetAttribute(emis_kernel, cudaFuncAttributeMaxDynamicSharedMemorySize,
                         EMIS_SMEM_BYTES);

    dim3 xg(256, 2);
    xproj_kernel<<<xg, 256, XP_SMEM_BYTES>>>(embed, seqs, W_ih_f, W_ih_b,
                                             b_ih_f, b_hh_f, b_ih_b, b_hh_b);
    wtrans_kernel<<<64, 256>>>(W_out);
    lstm_kernel<<<256, 128>>>(W_hh_f, W_hh_b, masks);
    emis_kernel<<<1024, 256, EMIS_SMEM_BYTES>>>(b_out);
    crf_kernel<<<64, 128>>>(tags, masks, start_trans, end_trans, trans);
    final_kernel<<<1, 32>>>((float*)d_out);
}

// round 16
// speedup vs baseline: 1.7205x; 1.3161x over previous
#include <cuda_runtime.h>
#include <cuda_bf16.h>
#include <cuda_fp16.h>

// Problem dims
#define SL 512   // sequence length L
#define NB 64    // batch
#define NE 256   // embed dim E
#define NH 256   // hidden H
#define NG 1024  // 4*H
#define NT 32    // tags T

// ---------------------------------------------------------------------------
// Packed f32x2 helpers (used by lstm/emis)
// ---------------------------------------------------------------------------
#define FMA2(acc, a, b) \
    asm("fma.rn.f32x2 %0, %1, %2, %0;" : "+l"(acc) : "l"(a), "l"(b))
#define ADD2(acc, v) \
    asm("add.rn.f32x2 %0, %0, %1;" : "+l"(acc) : "l"(v))
#define UNPK2(lo, hi, v) do { unsigned _a, _b; \
    asm("mov.b64 {%0, %1}, %2;" : "=r"(_a), "=r"(_b) : "l"(v)); \
    lo = __uint_as_float(_a); hi = __uint_as_float(_b); } while (0)
#define TANHA(d, x) asm("tanh.approx.f32 %0, %1;" : "=f"(d) : "f"(x))
#define H2F2(d, h2u) do { __half2 _h = *(__half2*)&(h2u); \
    float2 _f = __half22float2(_h); \
    asm("mov.b64 %0, {%1, %2};" : "=l"(d) : "f"(_f.x), "f"(_f.y)); } while (0)

// fp16 tensor-core mma: D(16x8,f32) += A(16x16,f16,row) * B(16x8,f16,col)
__device__ __forceinline__ void mma16816(
    float& c0, float& c1, float& c2, float& c3,
    unsigned a0, unsigned a1, unsigned a2, unsigned a3,
    unsigned b0, unsigned b1)
{
    asm volatile(
        "mma.sync.aligned.m16n8k16.row.col.f32.f16.f16.f32 "
        "{%0,%1,%2,%3}, {%4,%5,%6,%7}, {%8,%9}, {%0,%1,%2,%3};"
        : "+f"(c0), "+f"(c1), "+f"(c2), "+f"(c3)
        : "r"(a0), "r"(a1), "r"(a2), "r"(a3), "r"(b0), "r"(b1));
}

// ---------------------------------------------------------------------------
// Device-global scratch.  x_proj / h_out fp16; x_proj GATE-LAST [l][b][h][g].
// ---------------------------------------------------------------------------
__device__ __half    g_xproj[2][(size_t)SL * NB * NG];
__device__ __half    g_hout [2][(size_t)SL * NB * NH];
__device__ float     g_em   [(size_t)SL * NB * NT];
__device__ float     g_hbuf [2][2][NB * NH];
__device__ float     g_WoutT[512 * NT];
__device__ float     g_llh  [NB];
__device__ __half    g_Wih16[2][NG * NE];    // fp16 W_ih, gate-last rows
__device__ float     g_bias_gl[2][NG];       // gate-last b_ih + b_hh
// Peer-flag barrier: one monotonic flag per block, 16 blocks per group.
__device__ unsigned  g_flag[16][32];

// ---------------------------------------------------------------------------
// Kernel 0: prep — fp16 gate-last W_ih, fused gate-last bias, W_out^T.
// grid = 2048 x 256
// ---------------------------------------------------------------------------
__global__ void wprep_kernel(
    const float* __restrict__ Wf, const float* __restrict__ Wb,
    const float* __restrict__ bihf, const float* __restrict__ bhhf,
    const float* __restrict__ bihb, const float* __restrict__ bhhb,
    const float* __restrict__ Wout)
{
    int idx = blockIdx.x * 256 + threadIdx.x;      // 0..524287
    {
        int k = idx & 255, n = (idx >> 8) & 1023, dir = idx >> 18;
        const float* W = dir ? Wb : Wf;
        int wrow = (n & 3) * 256 + (n >> 2);
        g_Wih16[dir][n * 256 + k] = __float2half_rn(W[wrow * 256 + k]);
    }
    if (idx < 2048) {
        int dir = idx >> 10, n = idx & 1023;
        int wrow = (n & 3) * 256 + (n >> 2);
        g_bias_gl[dir][n] = dir ? (bihb[wrow] + bhhb[wrow])
                                : (bihf[wrow] + bhhf[wrow]);
    }
    if (idx < 512 * 32) {
        int k = idx >> 5, t = idx & 31;
        g_WoutT[idx] = Wout[t * 512 + k];
    }
}

// ---------------------------------------------------------------------------
// Kernel 1: x_proj via fp16 tensor cores.
// Block = 128 threads (4 warps), 128 gathered rows resident in smem fp16;
// loops 16 N-chunks of 64 gate-last columns.  Warp = 32 rows x 64 cols.
// grid = (256, 2).
// ---------------------------------------------------------------------------
#define APAD 264                       // halves per padded row (528B)
#define XPM_SMEM (128 * APAD * 2 + 64 * APAD * 2 + 64 * 4)   // 101632 B
__global__ __launch_bounds__(128) void xproj_kernel(
    const float* __restrict__ embed, const int* __restrict__ seqs)
{
    extern __shared__ __half xsm[];
    __half* As = xsm;                          // [128][APAD]
    __half* Ws = xsm + 128 * APAD;             // [64][APAD]
    float*  bs = (float*)(xsm + 192 * APAD);   // [64]

    const int tid  = threadIdx.x;
    const int bm   = blockIdx.x;               // 0..255 (M tile)
    const int dir  = blockIdx.y;
    const int w    = tid >> 5;
    const int lane = tid & 31;
    const int g8   = lane >> 2;                // 0..7
    const int tq   = lane & 3;                 // 0..3
    const int mbase = w * 32;

    // Stage A: thread = row; gather + convert fp32 -> fp16.
    {
        const float* src = embed + (long)seqs[bm * 128 + tid] * 256;
        __half* dst = As + tid * APAD;
#pragma unroll
        for (int k = 0; k < 256; k += 8) {
            float4 v0 = __ldg((const float4*)(src + k));
            float4 v1 = __ldg((const float4*)(src + k + 4));
            uint4 pk;
            *(__half2*)&pk.x = __floats2half2_rn(v0.x, v0.y);
            *(__half2*)&pk.y = __floats2half2_rn(v0.z, v0.w);
            *(__half2*)&pk.z = __floats2half2_rn(v1.x, v1.y);
            *(__half2*)&pk.w = __floats2half2_rn(v1.z, v1.w);
            *(uint4*)(dst + k) = pk;
        }
    }
    __syncthreads();

    __half* outp = g_xproj[dir];
    const uint4* wsrc0 = (const uint4*)g_Wih16[dir];

    for (int nc = 0; nc < 16; nc++) {
        // Stage W chunk (64 gate-last rows x 256 k, fp16) + bias.
        {
            const uint4* wsrc = wsrc0 + (size_t)nc * 64 * 32;   // 32 uint4/row
#pragma unroll
            for (int i = 0; i < 16; i++) {
                int idx = tid + i * 128;       // 0..2047
                int n = idx >> 5, c = idx & 31;
                uint4 v = __ldg(wsrc + idx);
                *(uint4*)(Ws + n * APAD + c * 8) = v;
            }
            if (tid < 64) bs[tid] = g_bias_gl[dir][nc * 64 + tid];
        }
        __syncthreads();

        float C[2][8][4];
#pragma unroll
        for (int mt = 0; mt < 2; mt++)
#pragma unroll
            for (int nt = 0; nt < 8; nt++)
#pragma unroll
                for (int q = 0; q < 4; q++) C[mt][nt][q] = 0.f;

#pragma unroll
        for (int ks = 0; ks < 16; ks++) {
            const int kb = ks * 16 + tq * 2;
            unsigned a[2][4];
#pragma unroll
            for (int mt = 0; mt < 2; mt++) {
                const __half* ab = As + (mbase + mt * 16 + g8) * APAD;
                a[mt][0] = *(const unsigned*)(ab + kb);
                a[mt][1] = *(const unsigned*)(ab + 8 * APAD + kb);
                a[mt][2] = *(const unsigned*)(ab + kb + 8);
                a[mt][3] = *(const unsigned*)(ab + 8 * APAD + kb + 8);
            }
#pragma unroll
            for (int nt = 0; nt < 8; nt++) {
                const __half* bp = Ws + (nt * 8 + g8) * APAD;
                unsigned b0 = *(const unsigned*)(bp + kb);
                unsigned b1 = *(const unsigned*)(bp + kb + 8);
                mma16816(C[0][nt][0], C[0][nt][1], C[0][nt][2], C[0][nt][3],
                         a[0][0], a[0][1], a[0][2], a[0][3], b0, b1);
                mma16816(C[1][nt][0], C[1][nt][1], C[1][nt][2], C[1][nt][3],
                         a[1][0], a[1][1], a[1][2], a[1][3], b0, b1);
            }
        }

        // Epilogue: add bias, convert fp16, store gate-last.
#pragma unroll
        for (int nt = 0; nt < 8; nt++) {
            const int ncol = nc * 64 + nt * 8 + tq * 2;
            const float bx = bs[nt * 8 + tq * 2];
            const float by = bs[nt * 8 + tq * 2 + 1];
#pragma unroll
            for (int mt = 0; mt < 2; mt++) {
                long r0 = (long)bm * 128 + mbase + mt * 16 + g8;
                __half2 h01 = __floats2half2_rn(C[mt][nt][0] + bx,
                                                C[mt][nt][1] + by);
                __half2 h23 = __floats2half2_rn(C[mt][nt][2] + bx,
                                                C[mt][nt][3] + by);
                *(__half2*)(outp + r0 * 1024 + ncol)       = h01;
                *(__half2*)(outp + (r0 + 8) * 1024 + ncol) = h23;
            }
        }
        __syncthreads();
    }
}

// ---------------------------------------------------------------------------
// Kernel 2: persistent BiLSTM (unchanged from passing R14 build).
// ---------------------------------------------------------------------------
__global__ __launch_bounds__(128, 2) void lstm_kernel(
    const float* __restrict__ Whhf, const float* __restrict__ Whhb,
    const int* __restrict__ masks)
{
    __shared__ float hsm[8 * 256];
    __shared__ unsigned long long psum[4096];

    const int tid  = threadIdx.x;
    const int lane = tid & 31;
    const int w    = tid >> 5;
    const int bid  = blockIdx.x;
    const int grp  = bid & 15;
    const int sub  = bid >> 4;
    const int dir  = grp >> 3;
    const int b0   = (grp & 7) * 8;
    const int h0   = sub * 16;
    const int hh   = lane & 15;
    const int ks   = w * 2 + (lane >> 4);
    const int bb   = tid >> 4;
    const int hh2  = tid & 15;

    const float* W = dir ? Whhb : Whhf;
    const __half* xp = g_xproj[dir];
    __half* outp = g_hout[dir];

    const unsigned base = *(volatile unsigned*)&g_flag[grp][sub];

    unsigned long long wr[4][16];
#pragma unroll
    for (int g = 0; g < 4; g++) {
        const float* wp = W + ((size_t)(g * 256 + h0 + hh)) * 256 + ks * 32;
#pragma unroll
        for (int u = 0; u < 16; u++)
            wr[g][u] = *(const unsigned long long*)(wp + u * 2);
    }

    g_hbuf[dir][0][(b0 + bb) * 256 + h0 + hh2] = 0.f;
    float hreg = 0.f, creg = 0.f;
    __threadfence();
    __syncthreads();
    if (tid == 0) *(volatile unsigned*)&g_flag[grp][sub] = base + 1u;

    float4* hsm4 = (float4*)hsm;
    const ulonglong2* hU2 = (const ulonglong2*)hsm;

    const int l0 = dir ? 511 : 0;
    uint2 xraw = __ldg((const uint2*)(
        xp + ((size_t)(l0 * 64 + b0 + bb) * 256 + (h0 + hh2)) * 4));
    int m = __ldg(masks + l0 * 64 + b0 + bb);

    int p = 0;
    for (int step = 0; step < 512; step++) {
        const int l = dir ? (511 - step) : step;

        {
            const unsigned target = base + 1u + (unsigned)step;
            if (tid < 16) {
                volatile unsigned* f = &g_flag[grp][tid];
                while ((int)(*f - target) < 0) { }
            }
            __syncthreads();
        }

        const float4* hb4 = (const float4*)g_hbuf[dir][p];
#pragma unroll
        for (int i = 0; i < 4; i++) {
            int idx = tid + i * 128;
            hsm4[idx] = __ldcg(hb4 + (b0 + (idx >> 6)) * 64 + (idx & 63));
        }
        __syncthreads();

#pragma unroll
        for (int pass = 0; pass < 2; pass++) {
            unsigned long long acc[4][4];
#pragma unroll
            for (int g = 0; g < 4; g++)
#pragma unroll
                for (int b = 0; b < 4; b++) acc[g][b] = 0ull;
#pragma unroll
            for (int b = 0; b < 4; b++) {
                const ulonglong2* hp = hU2 + (pass * 4 + b) * 64 + ks * 8;
#pragma unroll
                for (int u2 = 0; u2 < 8; u2++) {
                    ulonglong2 hv = hp[u2];
                    FMA2(acc[0][b], wr[0][2*u2], hv.x);
                    FMA2(acc[0][b], wr[0][2*u2+1], hv.y);
                    FMA2(acc[1][b], wr[1][2*u2], hv.x);
                    FMA2(acc[1][b], wr[1][2*u2+1], hv.y);
                    FMA2(acc[2][b], wr[2][2*u2], hv.x);
                    FMA2(acc[2][b], wr[2][2*u2+1], hv.y);
                    FMA2(acc[3][b], wr[3][2*u2], hv.x);
                    FMA2(acc[3][b], wr[3][2*u2+1], hv.y);
                }
            }
#pragma unroll
            for (int g = 0; g < 4; g++)
#pragma unroll
                for (int b = 0; b < 4; b++)
                    psum[((ks * 4 + g) * 8 + pass * 4 + b) * 16 + hh] = acc[g][b];
        }
        __syncthreads();

        unsigned long long s0 = 0ull, s1 = 0ull, s2 = 0ull, s3 = 0ull;
#pragma unroll
        for (int k2 = 0; k2 < 8; k2++) {
            ADD2(s0, psum[((k2 * 4 + 0) * 8 + bb) * 16 + hh2]);
            ADD2(s1, psum[((k2 * 4 + 1) * 8 + bb) * 16 + hh2]);
            ADD2(s2, psum[((k2 * 4 + 2) * 8 + bb) * 16 + hh2]);
            ADD2(s3, psum[((k2 * 4 + 3) * 8 + bb) * 16 + hh2]);
        }
        float lo, hi, f0, f1, f2, f3;
        UNPK2(lo, hi, s0); f0 = lo + hi;
        UNPK2(lo, hi, s1); f1 = lo + hi;
        UNPK2(lo, hi, s2); f2 = lo + hi;
        UNPK2(lo, hi, s3); f3 = lo + hi;

        float2 x01 = __half22float2(*(__half2*)&xraw.x);
        float2 x23 = __half22float2(*(__half2*)&xraw.y);

        float ti, tf, tg, to;
        TANHA(ti, 0.5f * (x01.x + f0));
        TANHA(tf, 0.5f * (x01.y + f1));
        TANHA(tg, x23.x + f2);
        TANHA(to, 0.5f * (x23.y + f3));
        float gi = fmaf(0.5f, ti, 0.5f);
        float gf = fmaf(0.5f, tf, 0.5f);
        float go = fmaf(0.5f, to, 0.5f);
        float cn = gf * creg + gi * tg;
        float tc; TANHA(tc, cn);
        float hn = go * tc;
        float outv;
        if (m) { creg = cn; hreg = hn; outv = hn; } else { outv = 0.f; }

        g_hbuf[dir][p ^ 1][(b0 + bb) * 256 + h0 + hh2] = hreg;
        __threadfence();
        __syncthreads();
        if (tid == 0)
            *(volatile unsigned*)&g_flag[grp][sub] = base + 2u + (unsigned)step;

        outp[((size_t)(l * 64 + b0 + bb)) * 256 + h0 + hh2] = __float2half_rn(outv);
        const int sn = (step < 511) ? step + 1 : 511;
        const int ln = dir ? (511 - sn) : sn;
        xraw = __ldg((const uint2*)(
            xp + ((size_t)(ln * 64 + b0 + bb) * 256 + (h0 + hh2)) * 4));
        m = __ldg(masks + ln * 64 + b0 + bb);

        p ^= 1;
    }
}

// ---------------------------------------------------------------------------
// Kernel 3: emissions (unchanged from passing R14 build).
// ---------------------------------------------------------------------------
#define WPADH 520
#define EMIS_SMEM_BYTES (32 * WPADH * 2 + 8 * 512 * 4)   // 49664
__global__ __launch_bounds__(256) void emis_kernel(const float* __restrict__ bout)
{
    extern __shared__ char esm[];
    __half* wsmT = (__half*)esm;
    float*  hsm  = (float*)(esm + 32 * WPADH * 2);
    const int tid = threadIdx.x;
    const int r = tid >> 5, t = tid & 31;
    const float bb = bout[t];

    for (int i = 0; i < 64; i++) {
        int idx = tid + i * 256;
        int k = idx >> 5, tt = idx & 31;
        wsmT[tt * WPADH + k] = __float2half_rn(g_WoutT[idx]);
    }

    const uint4* h0p = (const uint4*)g_hout[0];
    const uint4* h1p = (const uint4*)g_hout[1];

    for (int it = 0; it < 4; it++) {
        const int bm = blockIdx.x * 4 + it;
        __syncthreads();
#pragma unroll
        for (int i = 0; i < 2; i++) {
            int s = tid + i * 256;
            int rr = s >> 6, c8 = s & 63;
            size_t row = (size_t)bm * 8 + rr;
            uint4 v = (c8 < 32) ? __ldg(h0p + row * 32 + c8)
                                : __ldg(h1p + row * 32 + (c8 - 32));
            int cb = (c8 < 32) ? c8 * 8 : 256 + (c8 - 32) * 8;
            float* dst = hsm + rr * 512 + cb;
            float2 f0 = __half22float2(*(__half2*)&v.x);
            float2 f1 = __half22float2(*(__half2*)&v.y);
            float2 f2 = __half22float2(*(__half2*)&v.z);
            float2 f3 = __half22float2(*(__half2*)&v.w);
            *(float4*)dst       = make_float4(f0.x, f0.y, f1.x, f1.y);
            *(float4*)(dst + 4) = make_float4(f2.x, f2.y, f3.x, f3.y);
        }
        __syncthreads();

        const float*  hr = hsm + r * 512;
        const __half* wrh = wsmT + t * WPADH;
        unsigned long long a0 = 0ull, a1 = 0ull, a2 = 0ull, a3 = 0ull;
#pragma unroll 4
        for (int k = 0; k < 512; k += 16) {
            ulonglong2 hA = *(const ulonglong2*)(hr + k);
            ulonglong2 hB = *(const ulonglong2*)(hr + k + 4);
            ulonglong2 hC = *(const ulonglong2*)(hr + k + 8);
            ulonglong2 hD = *(const ulonglong2*)(hr + k + 12);
            uint2 wA = *(const uint2*)(wrh + k);
            uint2 wB = *(const uint2*)(wrh + k + 4);
            uint2 wC = *(const uint2*)(wrh + k + 8);
            uint2 wD = *(const uint2*)(wrh + k + 12);
            unsigned long long w0, w1, w2, w3, w4, w5, w6, w7;
            H2F2(w0, wA.x); H2F2(w1, wA.y);
            H2F2(w2, wB.x); H2F2(w3, wB.y);
            H2F2(w4, wC.x); H2F2(w5, wC.y);
            H2F2(w6, wD.x); H2F2(w7, wD.y);
            FMA2(a0, hA.x, w0); FMA2(a0, hA.y, w1);
            FMA2(a1, hB.x, w2); FMA2(a1, hB.y, w3);
            FMA2(a2, hC.x, w4); FMA2(a2, hC.y, w5);
            FMA2(a3, hD.x, w6); FMA2(a3, hD.y, w7);
        }
        ADD2(a0, a1); ADD2(a2, a3); ADD2(a0, a2);
        float lo, hi;
        UNPK2(lo, hi, a0);
        g_em[((size_t)bm * 8 + r) * 32 + t] = lo + hi + bb;
    }
}

// ---------------------------------------------------------------------------
// Kernel 4: CRF (unchanged).
// ---------------------------------------------------------------------------
__global__ __launch_bounds__(128) void crf_kernel(
    const int* __restrict__ tags, const int* __restrict__ masks,
    const float* __restrict__ start_trans, const float* __restrict__ end_trans,
    const float* __restrict__ trans)
{
    __shared__ float tsm[NT * NT];
    __shared__ float ssm[NT];
    __shared__ float pm[4][NT];
    __shared__ float ps[4][NT];
    __shared__ float redf[8];
    __shared__ int   redi[8];

    const int b = blockIdx.x;
    const int tid = threadIdx.x;
    const int w = tid >> 5;
    const int j = tid & 31;

    for (int i = tid; i < NT * NT; i += 128) tsm[i] = trans[i];
    if (w == 0) ssm[j] = start_trans[j] + g_em[(size_t)b * 32 + j];
    __syncthreads();

    for (int l = 1; l < 512; l++) {
        float v[8];
        float mx = -3.4e38f;
#pragma unroll
        for (int ii = 0; ii < 8; ii++) {
            int i = w * 8 + ii;
            v[ii] = ssm[i] + tsm[i * 32 + j];
            mx = fmaxf(mx, v[ii]);
        }
        float s = 0.f;
#pragma unroll
        for (int ii = 0; ii < 8; ii++) s += __expf(v[ii] - mx);
        pm[w][j] = mx;
        ps[w][j] = s;
        __syncthreads();
        if (w == 0) {
            float m0 = pm[0][j], m1 = pm[1][j], m2 = pm[2][j], m3 = pm[3][j];
            float M = fmaxf(fmaxf(m0, m1), fmaxf(m2, m3));
            float S = ps[0][j] * __expf(m0 - M) + ps[1][j] * __expf(m1 - M)
                    + ps[2][j] * __expf(m2 - M) + ps[3][j] * __expf(m3 - M);
            float nxt = M + __logf(S) + g_em[((size_t)(l * 64 + b)) * 32 + j];
            if (masks[l * 64 + b]) ssm[j] = nxt;
        }
        __syncthreads();
    }

    float part = 0.f;
    int lenp = 0;
    for (int l = tid; l < 512; l += 128) {
        int m = masks[l * 64 + b];
        lenp += m;
        int tg = tags[l * 64 + b];
        float e = g_em[((size_t)(l * 64 + b)) * 32 + tg];
        if (l == 0) {
            part += start_trans[tg] + e;
        } else {
            int tp = tags[(l - 1) * 64 + b];
            part += (e + tsm[tp * 32 + tg]) * (float)m;
        }
    }
#pragma unroll
    for (int off = 16; off > 0; off >>= 1) {
        part += __shfl_xor_sync(0xffffffffu, part, off);
        lenp += __shfl_xor_sync(0xffffffffu, lenp, off);
    }
    if (j == 0) { redf[w] = part; redi[w] = lenp; }
    __syncthreads();

    if (w == 0) {
        float num_p = redf[0] + redf[1] + redf[2] + redf[3];
        int   length = redi[0] + redi[1] + redi[2] + redi[3];

        float tv = ssm[j] + end_trans[j];
        float mx = tv;
#pragma unroll
        for (int off = 16; off > 0; off >>= 1)
            mx = fmaxf(mx, __shfl_xor_sync(0xffffffffu, mx, off));
        float ex = __expf(tv - mx);
#pragma unroll
        for (int off = 16; off > 0; off >>= 1)
            ex += __shfl_xor_sync(0xffffffffu, ex, off);
        float logz = mx + __logf(ex);

        if (j == 0) {
            int last = tags[(length - 1) * 64 + b];
            g_llh[b] = (num_p + end_trans[last]) - logz;
        }
    }
}

// ---------------------------------------------------------------------------
// Kernel 5: out = -mean(llh)
// ---------------------------------------------------------------------------
__global__ void final_kernel(float* __restrict__ out) {
    if (threadIdx.x == 0) {
        float s = 0.f;
        for (int i = 0; i < NB; i++) s += g_llh[i];
        out[0] = -s / (float)NB;
    }
}

// ---------------------------------------------------------------------------
extern "C" void kernel_launch(void* const* d_in, const int* in_sizes, int n_in,
                              void* d_out, int out_size) {
    const int*   seqs        = (const int*)d_in[0];
    const int*   tags        = (const int*)d_in[1];
    const int*   masks       = (const int*)d_in[2];
    const float* embed       = (const float*)d_in[3];
    const float* W_ih_f      = (const float*)d_in[4];
    const float* W_hh_f      = (const float*)d_in[5];
    const float* b_ih_f      = (const float*)d_in[6];
    const float* b_hh_f      = (const float*)d_in[7];
    const float* W_ih_b      = (const float*)d_in[8];
    const float* W_hh_b      = (const float*)d_in[9];
    const float* b_ih_b      = (const float*)d_in[10];
    const float* b_hh_b      = (const float*)d_in[11];
    const float* W_out       = (const float*)d_in[12];
    const float* b_out       = (const float*)d_in[13];
    const float* start_trans = (const float*)d_in[14];
    const float* end_trans   = (const float*)d_in[15];
    const float* trans       = (const float*)d_in[16];

    cudaFuncSetAttribute(xproj_kernel, cudaFuncAttributeMaxDynamicSharedMemorySize,
                         XPM_SMEM);
    cudaFuncSetAttribute(emis_kernel, cudaFuncAttributeMaxDynamicSharedMemorySize,
                         EMIS_SMEM_BYTES);

    wprep_kernel<<<2048, 256>>>(W_ih_f, W_ih_b, b_ih_f, b_hh_f,
                                b_ih_b, b_hh_b, W_out);
    dim3 xg(256, 2);
    xproj_kernel<<<xg, 128, XPM_SMEM>>>(embed, seqs);
    lstm_kernel<<<256, 128>>>(W_hh_f, W_hh_b, masks);
    emis_kernel<<<1024, 256, EMIS_SMEM_BYTES>>>(b_out);
    crf_kernel<<<64, 128>>>(tags, masks, start_trans, end_trans, trans);
    final_kernel<<<1, 32>>>((float*)d_out);
}